// round 13
// baseline (speedup 1.0000x reference)
#include <cuda_runtime.h>
#include <cstdint>

// Problem constants
#define BB 2
#define SS 2048
#define DD 1024
#define HH 16
#define DK 64
#define MROWS (BB * SS)   // 4096

// Scratch (static device globals — allocation-guard safe)
__device__ float g_q[MROWS * DD];
__device__ float g_k[MROWS * DD];
__device__ float g_v[MROWS * DD];
__device__ float g_o[MROWS * DD];

// ---------------------------------------------------------------------------
// Helpers
// ---------------------------------------------------------------------------
static __device__ __forceinline__ uint32_t f2tf32(float x) {
    uint32_t u;
    asm("cvt.rna.tf32.f32 %0, %1;" : "=r"(u) : "f"(x));
    return u;
}

static __device__ __forceinline__ float ex2f(float x) {
    float r;
    asm("ex2.approx.f32 %0, %1;" : "=f"(r) : "f"(x));
    return r;
}

static __device__ __forceinline__ uint32_t cvta_smem(const void* p) {
    uint32_t a;
    asm("{ .reg .u64 t; cvta.to.shared.u64 t, %1; cvt.u32.u64 %0, t; }"
        : "=r"(a) : "l"(p));
    return a;
}

static __device__ __forceinline__ void mma_tf32(float c[4], const uint32_t a[4],
                                                uint32_t b0, uint32_t b1) {
    asm volatile(
        "mma.sync.aligned.m16n8k8.row.col.f32.tf32.tf32.f32 "
        "{%0,%1,%2,%3}, {%4,%5,%6,%7}, {%8,%9}, {%0,%1,%2,%3};"
        : "+f"(c[0]), "+f"(c[1]), "+f"(c[2]), "+f"(c[3])
        : "r"(a[0]), "r"(a[1]), "r"(a[2]), "r"(a[3]), "r"(b0), "r"(b1));
}

static __device__ __forceinline__ void ldsm_x4(uint32_t r[4], uint32_t addr) {
    asm volatile("ldmatrix.sync.aligned.m8n8.x4.shared.b16 {%0,%1,%2,%3}, [%4];"
        : "=r"(r[0]), "=r"(r[1]), "=r"(r[2]), "=r"(r[3]) : "r"(addr));
}

// ---------------------------------------------------------------------------
// Fused tf32 mma.sync GEMM (R6 config): C[z] = A[z] @ W[z]^T + bias[z].
// CTA 128x128, BK=16, 128 threads (4 warps of 64x64). doRound: tf32-round C.
// ---------------------------------------------------------------------------
#define BK 16
#define APAD 20
#define GBUF (128 * APAD)

__global__ __launch_bounds__(128, 2) void gemm3_mma_kernel(
    const float* __restrict__ A0, const float* __restrict__ A1, const float* __restrict__ A2,
    const float* __restrict__ W0, const float* __restrict__ W1, const float* __restrict__ W2,
    const float* __restrict__ b0p, const float* __restrict__ b1p, const float* __restrict__ b2p,
    float* __restrict__ C0, float* __restrict__ C1, float* __restrict__ C2,
    int doRound)
{
    __shared__ uint32_t As[2][GBUF];
    __shared__ uint32_t Bs[2][GBUF];

    const int z = blockIdx.z;
    const float* A = (z == 0) ? A0 : (z == 1) ? A1 : A2;
    const float* W = (z == 0) ? W0 : (z == 1) ? W1 : W2;
    const float* bias = (z == 0) ? b0p : (z == 1) ? b1p : b2p;
    float* C = (z == 0) ? C0 : (z == 1) ? C1 : C2;

    const int tid = threadIdx.x;
    const int lane = tid & 31;
    const int wid = tid >> 5;
    const int wm = wid & 1;
    const int wn = wid >> 1;
    const int l4 = lane >> 2;
    const int lm = lane & 3;
    const int rowBase = blockIdx.y * 128;
    const int colBase = blockIdx.x * 128;

    const uint32_t asb = cvta_smem(As);
    const uint32_t bsb = cvta_smem(Bs);

    uint32_t aOff[4], bOff[4];
#pragma unroll
    for (int mt = 0; mt < 4; mt++)
        aOff[mt] = ((wm * 64 + mt * 16 + (lane & 15)) * APAD + ((lane >> 4) << 2)) * 4;
#pragma unroll
    for (int t = 0; t < 4; t++)
        bOff[t] = ((wn * 64 + t * 16 + (lane & 7) + 8 * ((lane >> 4) & 1)) * APAD
                   + 4 * ((lane >> 3) & 1)) * 4;

    float acc[4][8][4];
#pragma unroll
    for (int mt = 0; mt < 4; mt++)
#pragma unroll
        for (int nt = 0; nt < 8; nt++)
#pragma unroll
            for (int r = 0; r < 4; r++) acc[mt][nt][r] = 0.0f;

    float4 ra[4], rb[4];
    auto loadg = [&](int ic) {
        const int kOff = ic * BK;
#pragma unroll
        for (int i = 0; i < 4; i++) {
            int fi = tid + 128 * i;
            int row = fi >> 2;
            int k4 = fi & 3;
            ra[i] = *(const float4*)(A + (size_t)(rowBase + row) * DD + kOff + k4 * 4);
            rb[i] = *(const float4*)(W + (size_t)(colBase + row) * DD + kOff + k4 * 4);
        }
    };

    loadg(0);
    const int nChunks = DD / BK;

    for (int ic = 0; ic < nChunks; ic++) {
        const int buf = ic & 1;
        const uint32_t bufB = buf * (GBUF * 4);
#pragma unroll
        for (int i = 0; i < 4; i++) {
            int fi = tid + 128 * i;
            int row = fi >> 2;
            int k4 = fi & 3;
            uint32_t* da = &As[buf][row * APAD + k4 * 4];
            da[0] = f2tf32(ra[i].x); da[1] = f2tf32(ra[i].y);
            da[2] = f2tf32(ra[i].z); da[3] = f2tf32(ra[i].w);
            uint32_t* db = &Bs[buf][row * APAD + k4 * 4];
            db[0] = f2tf32(rb[i].x); db[1] = f2tf32(rb[i].y);
            db[2] = f2tf32(rb[i].z); db[3] = f2tf32(rb[i].w);
        }
        __syncthreads();

        if (ic + 1 < nChunks) loadg(ic + 1);

#pragma unroll
        for (int ks = 0; ks < 2; ks++) {
            const uint32_t kbB = ks * 32;
            uint32_t af[4][4];
#pragma unroll
            for (int mt = 0; mt < 4; mt++)
                ldsm_x4(af[mt], asb + bufB + aOff[mt] + kbB);
#pragma unroll
            for (int t = 0; t < 4; t++) {
                uint32_t bb[4];
                ldsm_x4(bb, bsb + bufB + bOff[t] + kbB);
#pragma unroll
                for (int mt = 0; mt < 4; mt++) {
                    mma_tf32(acc[mt][2 * t],     af[mt], bb[0], bb[1]);
                    mma_tf32(acc[mt][2 * t + 1], af[mt], bb[2], bb[3]);
                }
            }
        }
    }

#pragma unroll
    for (int nt = 0; nt < 8; nt++) {
        int c = colBase + wn * 64 + nt * 8 + 2 * lm;
        float2 bv = *(const float2*)(bias + c);
#pragma unroll
        for (int mt = 0; mt < 4; mt++) {
            int r = rowBase + wm * 64 + mt * 16 + l4;
            float2 o0 = make_float2(acc[mt][nt][0] + bv.x, acc[mt][nt][1] + bv.y);
            float2 o1 = make_float2(acc[mt][nt][2] + bv.x, acc[mt][nt][3] + bv.y);
            if (doRound) {
                o0.x = __uint_as_float(f2tf32(o0.x)); o0.y = __uint_as_float(f2tf32(o0.y));
                o1.x = __uint_as_float(f2tf32(o1.x)); o1.y = __uint_as_float(f2tf32(o1.y));
            }
            *(float2*)(C + (size_t)r * DD + c) = o0;
            *(float2*)(C + (size_t)(r + 8) * DD + c) = o1;
        }
    }
}

// ---------------------------------------------------------------------------
// Flash attention (causal), tf32 mma.sync, SOFTWARE-PIPELINED:
// S-MMA of tile kt+1 issues before softmax of tile kt (independent work that
// covers the softmax latency chain). 3-stage K/V smem ring, swizzled 256B-row
// layout (no padding), reg-prefetched loads, one barrier per tile.
// 128 threads (4 warps x 16 q-rows), 64 q-rows/CTA, 64-key tiles.
// ---------------------------------------------------------------------------
#define KTB 16384
#define FLASH_SMEM (7 * KTB)              // 3 K + 3 V + P = 114688 B
#define SCALE_LOG2E 0.180336880f          // 0.125 * log2(e)

__global__ __launch_bounds__(128, 2) void flash_pipe_kernel(
    const float* __restrict__ Qg, const float* __restrict__ Kg,
    const float* __restrict__ Vg, float* __restrict__ Og)
{
    extern __shared__ uint32_t sm[];

    const int tid = threadIdx.x;
    const int lane = tid & 31;
    const int wid = tid >> 5;
    const int l4 = lane >> 2;
    const int lm = lane & 3;

    const int qt = (gridDim.x - 1) - blockIdx.x;   // heavy tiles first
    const int h  = blockIdx.y;
    const int b  = blockIdx.z;
    const int q0 = qt * 64;

    const size_t base = (size_t)b * SS * DD + (size_t)h * DK;

    const int gr0 = q0 + wid * 16 + l4;
    const int prow = wid * 16 + l4;

    const uint32_t smb = cvta_smem(sm);
    const uint32_t vsb = smb + 3 * KTB;
    const uint32_t psb = smb + 6 * KTB;

    // B-fragment (K / Vt) ldsm addressing, swizzled 256B rows
    uint32_t rowB[4], swB[4];
#pragma unroll
    for (int t = 0; t < 4; t++) {
        uint32_t r = t * 16 + (lane & 7) + 8 * ((lane >> 4) & 1);
        rowB[t] = r * 256;
        swB[t] = r & 7;
    }
    const uint32_t cbb = (lane >> 3) & 1;
    // P A-fragment addressing
    const uint32_t rowP = wid * 16 + (lane & 15);
    const uint32_t pRowOff = rowP * 256;
    const uint32_t swP = rowP & 7;
    const uint32_t ca = lane >> 4;
    // P write addressing
    const uint32_t pw0 = psb + prow * 256 + (lm & 1) * 8;
    const uint32_t pw1 = psb + (prow + 8) * 256 + (lm & 1) * 8;
    const uint32_t swW0 = prow & 7;
    const uint32_t swW1 = (prow + 8) & 7;

    // Q fragments: bit-copy of pre-rounded tf32, premul by scale*log2e, re-round
    uint32_t qf[8][4];
#pragma unroll
    for (int ks = 0; ks < 8; ks++) {
        const float* q0p = Qg + base + (size_t)gr0 * DD;
        const float* q1p = Qg + base + (size_t)(gr0 + 8) * DD;
        qf[ks][0] = f2tf32(q0p[ks * 8 + lm]     * SCALE_LOG2E);
        qf[ks][1] = f2tf32(q1p[ks * 8 + lm]     * SCALE_LOG2E);
        qf[ks][2] = f2tf32(q0p[ks * 8 + lm + 4] * SCALE_LOG2E);
        qf[ks][3] = f2tf32(q1p[ks * 8 + lm + 4] * SCALE_LOG2E);
    }

    float oacc[8][4];
#pragma unroll
    for (int dt = 0; dt < 8; dt++)
#pragma unroll
        for (int r = 0; r < 4; r++) oacc[dt][r] = 0.0f;
    float m0 = -1e30f, m1 = -1e30f, l0 = 0.0f, l1 = 0.0f;

    // K/V register prefetch (bit copies)
    uint4 kr[8];
    uint32_t vr[32];
    const uint32_t* Ku = (const uint32_t*)Kg;
    const uint32_t* Vu = (const uint32_t*)Vg;
    auto load_kv = [&](int kt) {
        const int k0 = kt * 64;
#pragma unroll
        for (int i = 0; i < 8; i++) {
            int fi = tid + 128 * i;
            int row = fi >> 4;
            int c4 = (fi & 15) * 4;
            kr[i] = *(const uint4*)(Ku + base + (size_t)(k0 + row) * DD + c4);
        }
#pragma unroll
        for (int i = 0; i < 32; i++) {
            int fi = tid + 128 * i;
            int row = fi >> 6;
            int d = fi & 63;
            vr[i] = Vu[base + (size_t)(k0 + row) * DD + d];
        }
    };
    auto store_kv = [&](int buf) {
        const uint32_t kb = smb + buf * KTB;
        const uint32_t vb = vsb + buf * KTB;
#pragma unroll
        for (int i = 0; i < 8; i++) {
            int fi = tid + 128 * i;
            uint32_t row = fi >> 4;
            uint32_t ch = fi & 15;
            uint32_t a = kb + row * 256 + ((ch ^ (row & 7)) << 4);
            asm volatile("st.shared.v4.b32 [%0], {%1,%2,%3,%4};"
                :: "r"(a), "r"(kr[i].x), "r"(kr[i].y), "r"(kr[i].z), "r"(kr[i].w)
                : "memory");
        }
#pragma unroll
        for (int i = 0; i < 32; i++) {
            int fi = tid + 128 * i;
            uint32_t srow = fi >> 6;
            uint32_t d = fi & 63;
            uint32_t a = vb + d * 256 + ((((srow >> 2) ^ (d & 7))) << 4) + (srow & 3) * 4;
            asm volatile("st.shared.b32 [%0], %1;" :: "r"(a), "r"(vr[i]) : "memory");
        }
    };

    auto s_mma = [&](float (&sf)[8][4], uint32_t kbuf) {
#pragma unroll
        for (int nt = 0; nt < 8; nt++)
#pragma unroll
            for (int r = 0; r < 4; r++) sf[nt][r] = 0.0f;
#pragma unroll
        for (int ks = 0; ks < 8; ks++) {
            const uint32_t ck = cbb + ks * 2;
#pragma unroll
            for (int t = 0; t < 4; t++) {
                uint32_t bb[4];
                ldsm_x4(bb, kbuf + rowB[t] + ((ck ^ swB[t]) << 4));
                mma_tf32(sf[2 * t],     qf[ks], bb[0], bb[1]);
                mma_tf32(sf[2 * t + 1], qf[ks], bb[2], bb[3]);
            }
        }
    };

    const int nkt = qt + 1;

    // Prologue: tiles 0 and 1 staged; S(0) computed.
    float sfA[8][4], sfB[8][4];
    load_kv(0);
    store_kv(0);
    if (nkt > 1) load_kv(1);
    __syncthreads();
    s_mma(sfA, smb);                    // S(0) from buf 0
    if (nkt > 1) {
        store_kv(1);
        __syncthreads();
        if (nkt > 2) load_kv(2);
    }

    for (int kt = 0; kt < nkt; kt++) {
        const int k0 = kt * 64;
        const int bufC = kt % 3;
        const int bufN = (kt + 1) % 3;
        const int bufW = (kt + 2) % 3;

        // Independent tensor work first: S(kt+1) — covers softmax(kt) latency
        if (kt + 1 < nkt) s_mma(sfB, smb + bufN * KTB);

        // Causal mask on S(kt)
        if (k0 + 63 > q0 + wid * 16) {
#pragma unroll
            for (int nt = 0; nt < 8; nt++) {
                int c = k0 + nt * 8 + 2 * lm;
                if (c     > gr0)     sfA[nt][0] = -1e30f;
                if (c + 1 > gr0)     sfA[nt][1] = -1e30f;
                if (c     > gr0 + 8) sfA[nt][2] = -1e30f;
                if (c + 1 > gr0 + 8) sfA[nt][3] = -1e30f;
            }
        }

        // online softmax (log2 domain)
        float rm0 = -1e30f, rm1 = -1e30f;
#pragma unroll
        for (int nt = 0; nt < 8; nt++) {
            rm0 = fmaxf(rm0, fmaxf(sfA[nt][0], sfA[nt][1]));
            rm1 = fmaxf(rm1, fmaxf(sfA[nt][2], sfA[nt][3]));
        }
#pragma unroll
        for (int off = 1; off <= 2; off <<= 1) {
            rm0 = fmaxf(rm0, __shfl_xor_sync(0xffffffffu, rm0, off));
            rm1 = fmaxf(rm1, __shfl_xor_sync(0xffffffffu, rm1, off));
        }
        float nm0 = fmaxf(m0, rm0), nm1 = fmaxf(m1, rm1);
        float a0 = ex2f(m0 - nm0), a1 = ex2f(m1 - nm1);
        float rs0 = 0.0f, rs1 = 0.0f;
#pragma unroll
        for (int nt = 0; nt < 8; nt++) {
            sfA[nt][0] = ex2f(sfA[nt][0] - nm0);
            sfA[nt][1] = ex2f(sfA[nt][1] - nm0);
            sfA[nt][2] = ex2f(sfA[nt][2] - nm1);
            sfA[nt][3] = ex2f(sfA[nt][3] - nm1);
            rs0 += sfA[nt][0] + sfA[nt][1];
            rs1 += sfA[nt][2] + sfA[nt][3];
        }
#pragma unroll
        for (int off = 1; off <= 2; off <<= 1) {
            rs0 += __shfl_xor_sync(0xffffffffu, rs0, off);
            rs1 += __shfl_xor_sync(0xffffffffu, rs1, off);
        }
        l0 = l0 * a0 + rs0;  m0 = nm0;
        l1 = l1 * a1 + rs1;  m1 = nm1;
#pragma unroll
        for (int dt = 0; dt < 8; dt++) {
            oacc[dt][0] *= a0; oacc[dt][1] *= a0;
            oacc[dt][2] *= a1; oacc[dt][3] *= a1;
        }

        // P -> smem (tf32 bits), swizzled, warp-private rows
#pragma unroll
        for (int nt = 0; nt < 8; nt++) {
            uint32_t chunk = nt * 2 + (lm >> 1);
            uint2 p0 = make_uint2(f2tf32(sfA[nt][0]), f2tf32(sfA[nt][1]));
            uint2 p1 = make_uint2(f2tf32(sfA[nt][2]), f2tf32(sfA[nt][3]));
            asm volatile("st.shared.v2.b32 [%0], {%1,%2};"
                :: "r"(pw0 + ((chunk ^ swW0) << 4)), "r"(p0.x), "r"(p0.y) : "memory");
            asm volatile("st.shared.v2.b32 [%0], {%1,%2};"
                :: "r"(pw1 + ((chunk ^ swW1) << 4)), "r"(p1.x), "r"(p1.y) : "memory");
        }
        __syncwarp();

        // O += P @ V(kt)
        const uint32_t vBuf = vsb + bufC * KTB;
#pragma unroll
        for (int ks = 0; ks < 8; ks++) {
            uint32_t af[4];
            ldsm_x4(af, psb + pRowOff + (((ca + ks * 2) ^ swP) << 4));
            const uint32_t ck = cbb + ks * 2;
#pragma unroll
            for (int t = 0; t < 4; t++) {
                uint32_t bb[4];
                ldsm_x4(bb, vBuf + rowB[t] + ((ck ^ swB[t]) << 4));
                mma_tf32(oacc[2 * t],     af, bb[0], bb[1]);
                mma_tf32(oacc[2 * t + 1], af, bb[2], bb[3]);
            }
        }

        if (kt + 2 < nkt) store_kv(bufW);   // slot of tile kt-1 (free by barrier)
        if (kt + 3 < nkt) load_kv(kt + 3);  // LDGs fly across the barrier
        if (kt + 1 < nkt) {
            __syncthreads();
            // rotate S fragments
#pragma unroll
            for (int nt = 0; nt < 8; nt++)
#pragma unroll
                for (int r = 0; r < 4; r++) sfA[nt][r] = sfB[nt][r];
        }
    }

    float inv0 = 1.0f / l0, inv1 = 1.0f / l1;
#pragma unroll
    for (int dt = 0; dt < 8; dt++) {
        int d = dt * 8 + 2 * lm;
        float2 o0 = make_float2(oacc[dt][0] * inv0, oacc[dt][1] * inv0);
        float2 o1 = make_float2(oacc[dt][2] * inv1, oacc[dt][3] * inv1);
        *(float2*)(Og + base + (size_t)gr0 * DD + d) = o0;
        *(float2*)(Og + base + (size_t)(gr0 + 8) * DD + d) = o1;
    }
}

// ---------------------------------------------------------------------------
// Launch
// ---------------------------------------------------------------------------
extern "C" void kernel_launch(void* const* d_in, const int* in_sizes, int n_in,
                              void* d_out, int out_size)
{
    const float* query = (const float*)d_in[0];
    const float* key   = (const float*)d_in[1];
    const float* value = (const float*)d_in[2];
    const float* wq = (const float*)d_in[3];
    const float* bq = (const float*)d_in[4];
    const float* wk = (const float*)d_in[5];
    const float* bk = (const float*)d_in[6];
    const float* wv = (const float*)d_in[7];
    const float* bv = (const float*)d_in[8];
    const float* wo = (const float*)d_in[9];
    const float* bo = (const float*)d_in[10];
    float* out = (float*)d_out;

    float *q_s, *k_s, *v_s, *o_s;
    cudaGetSymbolAddress((void**)&q_s, g_q);
    cudaGetSymbolAddress((void**)&k_s, g_k);
    cudaGetSymbolAddress((void**)&v_s, g_v);
    cudaGetSymbolAddress((void**)&o_s, g_o);

    cudaFuncSetAttribute(flash_pipe_kernel,
                         cudaFuncAttributeMaxDynamicSharedMemorySize, FLASH_SMEM);

    // 1. fused q/k/v projections (outputs tf32-rounded)
    dim3 gproj3(DD / 128, MROWS / 128, 3);
    gemm3_mma_kernel<<<gproj3, 128>>>(query, key, value, wq, wk, wv,
                                      bq, bk, bv, q_s, k_s, v_s, 1);

    // 2. flash attention (pipelined)
    dim3 gattn(SS / 64, HH, BB);   // (32, 16, 2) = 1024 CTAs
    flash_pipe_kernel<<<gattn, 128, FLASH_SMEM>>>(q_s, k_s, v_s, o_s);

    // 3. output projection (full fp32 output)
    dim3 gproj1(DD / 128, MROWS / 128, 1);
    gemm3_mma_kernel<<<gproj1, 128>>>(o_s, o_s, o_s, wo, wo, wo,
                                      bo, bo, bo, out, out, out, 0);
}

// round 14
// speedup vs baseline: 1.0043x; 1.0043x over previous
#include <cuda_runtime.h>
#include <cstdint>

// Problem constants
#define BB 2
#define SS 2048
#define DD 1024
#define HH 16
#define DK 64
#define MROWS (BB * SS)   // 4096

// Scratch (static device globals — allocation-guard safe)
__device__ float g_q[MROWS * DD];
__device__ float g_k[MROWS * DD];
__device__ float g_v[MROWS * DD];
__device__ float g_o[MROWS * DD];
__device__ uint32_t g_wt[4 * DD * DD];   // tf32 pre-converted weights

// ---------------------------------------------------------------------------
// Helpers
// ---------------------------------------------------------------------------
static __device__ __forceinline__ uint32_t f2tf32(float x) {
    uint32_t u;
    asm("cvt.rna.tf32.f32 %0, %1;" : "=r"(u) : "f"(x));
    return u;
}

static __device__ __forceinline__ float ex2f(float x) {
    float r;
    asm("ex2.approx.f32 %0, %1;" : "=f"(r) : "f"(x));
    return r;
}

static __device__ __forceinline__ uint32_t cvta_smem(const void* p) {
    uint32_t a;
    asm("{ .reg .u64 t; cvta.to.shared.u64 t, %1; cvt.u32.u64 %0, t; }"
        : "=r"(a) : "l"(p));
    return a;
}

static __device__ __forceinline__ void mma_tf32(float c[4], const uint32_t a[4],
                                                uint32_t b0, uint32_t b1) {
    asm volatile(
        "mma.sync.aligned.m16n8k8.row.col.f32.tf32.tf32.f32 "
        "{%0,%1,%2,%3}, {%4,%5,%6,%7}, {%8,%9}, {%0,%1,%2,%3};"
        : "+f"(c[0]), "+f"(c[1]), "+f"(c[2]), "+f"(c[3])
        : "r"(a[0]), "r"(a[1]), "r"(a[2]), "r"(a[3]), "r"(b0), "r"(b1));
}

static __device__ __forceinline__ void ldsm_x4(uint32_t r[4], uint32_t addr) {
    asm volatile("ldmatrix.sync.aligned.m8n8.x4.shared.b16 {%0,%1,%2,%3}, [%4];"
        : "=r"(r[0]), "=r"(r[1]), "=r"(r[2]), "=r"(r[3]) : "r"(addr));
}

// ---------------------------------------------------------------------------
// Prepass: 4 weight matrices fp32 -> tf32(rna) bits. 16MB total, ~5us.
// ---------------------------------------------------------------------------
__global__ __launch_bounds__(256) void cvt_w_kernel(
    const float* __restrict__ w0, const float* __restrict__ w1,
    const float* __restrict__ w2, const float* __restrict__ w3,
    uint32_t* __restrict__ dst)
{
    const int y = blockIdx.y;
    const float* w = (y == 0) ? w0 : (y == 1) ? w1 : (y == 2) ? w2 : w3;
    const int idx = blockIdx.x * 256 + threadIdx.x;   // float4 index
    float4 v = *(const float4*)(w + (size_t)idx * 4);
    uint4 o = make_uint4(f2tf32(v.x), f2tf32(v.y), f2tf32(v.z), f2tf32(v.w));
    *(uint4*)(dst + (size_t)y * DD * DD + (size_t)idx * 4) = o;
}

// ---------------------------------------------------------------------------
// Fused tf32 mma.sync GEMM: C[z] = A[z] @ W[z]^T + bias[z].
// CTA 128x128, BK=16, 128 threads (4 warps of 64x64).
// B is pre-converted tf32 bits (bit-copy staging). ACVT: convert A or bit-copy.
// ---------------------------------------------------------------------------
#define BK 16
#define APAD 20
#define GBUF (128 * APAD)

template <int ACVT>
__global__ __launch_bounds__(128, 2) void gemm_mma_kernel(
    const float* __restrict__ A0, const float* __restrict__ A1, const float* __restrict__ A2,
    const uint32_t* __restrict__ Wt,
    const float* __restrict__ b0p, const float* __restrict__ b1p, const float* __restrict__ b2p,
    float* __restrict__ C0, float* __restrict__ C1, float* __restrict__ C2,
    int doRound)
{
    __shared__ uint32_t As[2][GBUF];
    __shared__ uint32_t Bs[2][GBUF];

    const int z = blockIdx.z;
    const float* A = (z == 0) ? A0 : (z == 1) ? A1 : A2;
    const uint32_t* W = Wt + (size_t)z * DD * DD;
    const float* bias = (z == 0) ? b0p : (z == 1) ? b1p : b2p;
    float* C = (z == 0) ? C0 : (z == 1) ? C1 : C2;

    const int tid = threadIdx.x;
    const int lane = tid & 31;
    const int wid = tid >> 5;
    const int wm = wid & 1;
    const int wn = wid >> 1;
    const int l4 = lane >> 2;
    const int lm = lane & 3;
    const int rowBase = blockIdx.y * 128;
    const int colBase = blockIdx.x * 128;

    const uint32_t asb = cvta_smem(As);
    const uint32_t bsb = cvta_smem(Bs);

    uint32_t aOff[4], bOff[4];
#pragma unroll
    for (int mt = 0; mt < 4; mt++)
        aOff[mt] = ((wm * 64 + mt * 16 + (lane & 15)) * APAD + ((lane >> 4) << 2)) * 4;
#pragma unroll
    for (int t = 0; t < 4; t++)
        bOff[t] = ((wn * 64 + t * 16 + (lane & 7) + 8 * ((lane >> 4) & 1)) * APAD
                   + 4 * ((lane >> 3) & 1)) * 4;

    float acc[4][8][4];
#pragma unroll
    for (int mt = 0; mt < 4; mt++)
#pragma unroll
        for (int nt = 0; nt < 8; nt++)
#pragma unroll
            for (int r = 0; r < 4; r++) acc[mt][nt][r] = 0.0f;

    // persistent global pointers, advanced by BK each chunk
    const uint32_t* aP[4];
    const uint32_t* bP[4];
#pragma unroll
    for (int i = 0; i < 4; i++) {
        int fi = tid + 128 * i;
        int row = fi >> 2;
        int k4 = fi & 3;
        aP[i] = (const uint32_t*)A + (size_t)(rowBase + row) * DD + k4 * 4;
        bP[i] = W + (size_t)(colBase + row) * DD + k4 * 4;
    }

    uint4 ra[4], rb[4];
    auto loadg = [&]() {
#pragma unroll
        for (int i = 0; i < 4; i++) {
            ra[i] = *(const uint4*)aP[i];  aP[i] += BK;
            rb[i] = *(const uint4*)bP[i];  bP[i] += BK;
        }
    };

    loadg();
    const int nChunks = DD / BK;

    for (int ic = 0; ic < nChunks; ic++) {
        const int buf = ic & 1;
        const uint32_t bufB = buf * (GBUF * 4);
#pragma unroll
        for (int i = 0; i < 4; i++) {
            int fi = tid + 128 * i;
            int row = fi >> 2;
            int k4 = fi & 3;
            uint32_t* da = &As[buf][row * APAD + k4 * 4];
            if (ACVT) {
                da[0] = f2tf32(__uint_as_float(ra[i].x));
                da[1] = f2tf32(__uint_as_float(ra[i].y));
                da[2] = f2tf32(__uint_as_float(ra[i].z));
                da[3] = f2tf32(__uint_as_float(ra[i].w));
            } else {
                da[0] = ra[i].x; da[1] = ra[i].y;
                da[2] = ra[i].z; da[3] = ra[i].w;
            }
            uint32_t* db = &Bs[buf][row * APAD + k4 * 4];
            db[0] = rb[i].x; db[1] = rb[i].y;
            db[2] = rb[i].z; db[3] = rb[i].w;
        }
        __syncthreads();

        if (ic + 1 < nChunks) loadg();

#pragma unroll
        for (int ks = 0; ks < 2; ks++) {
            const uint32_t kbB = ks * 32;
            uint32_t af[4][4];
#pragma unroll
            for (int mt = 0; mt < 4; mt++)
                ldsm_x4(af[mt], asb + bufB + aOff[mt] + kbB);
#pragma unroll
            for (int t = 0; t < 4; t++) {
                uint32_t bb[4];
                ldsm_x4(bb, bsb + bufB + bOff[t] + kbB);
#pragma unroll
                for (int mt = 0; mt < 4; mt++) {
                    mma_tf32(acc[mt][2 * t],     af[mt], bb[0], bb[1]);
                    mma_tf32(acc[mt][2 * t + 1], af[mt], bb[2], bb[3]);
                }
            }
        }
        // no trailing sync: double-buffered smem
    }

#pragma unroll
    for (int nt = 0; nt < 8; nt++) {
        int c = colBase + wn * 64 + nt * 8 + 2 * lm;
        float2 bv = *(const float2*)(bias + c);
#pragma unroll
        for (int mt = 0; mt < 4; mt++) {
            int r = rowBase + wm * 64 + mt * 16 + l4;
            float2 o0 = make_float2(acc[mt][nt][0] + bv.x, acc[mt][nt][1] + bv.y);
            float2 o1 = make_float2(acc[mt][nt][2] + bv.x, acc[mt][nt][3] + bv.y);
            if (doRound) {
                o0.x = __uint_as_float(f2tf32(o0.x)); o0.y = __uint_as_float(f2tf32(o0.y));
                o1.x = __uint_as_float(f2tf32(o1.x)); o1.y = __uint_as_float(f2tf32(o1.y));
            }
            *(float2*)(C + (size_t)r * DD + c) = o0;
            *(float2*)(C + (size_t)(r + 8) * DD + c) = o1;
        }
    }
}

// ---------------------------------------------------------------------------
// Flash attention (causal) — exact R12 winner: 128 threads (4 warps x 16
// q-rows), 64 q-rows/CTA, 64-key tiles, double-buffered K/V smem, single sync
// per tile, bit-copy staging (inputs pre-rounded tf32), log2-domain softmax.
// ---------------------------------------------------------------------------
#define FS 68
#define FLASH_SMEM ((4 * 64 + 64) * FS * 4)   // 87040 B
#define SCALE_LOG2E 0.180336880f              // 0.125 * log2(e)

__global__ __launch_bounds__(128, 2) void flash_mma_kernel(
    const float* __restrict__ Qg, const float* __restrict__ Kg,
    const float* __restrict__ Vg, float* __restrict__ Og)
{
    extern __shared__ uint32_t sm[];
    uint32_t* Ps = sm + 4 * 64 * FS;   // [64][FS]

    const int tid = threadIdx.x;
    const int lane = tid & 31;
    const int wid = tid >> 5;          // 0..3
    const int l4 = lane >> 2;
    const int lm = lane & 3;

    const int qt = (gridDim.x - 1) - blockIdx.x;   // heavy tiles first
    const int h  = blockIdx.y;
    const int b  = blockIdx.z;
    const int q0 = qt * 64;

    const size_t base = (size_t)b * SS * DD + (size_t)h * DK;

    const int gr0 = q0 + wid * 16 + l4;
    const int prow = wid * 16 + l4;

    const uint32_t smb = cvta_smem(sm);
    const uint32_t psb = smb + 4 * 64 * FS * 4;

    uint32_t kvOff[4];
#pragma unroll
    for (int t = 0; t < 4; t++)
        kvOff[t] = ((t * 16 + (lane & 7) + 8 * ((lane >> 4) & 1)) * FS
                    + 4 * ((lane >> 3) & 1)) * 4;
    const uint32_t pOff = ((wid * 16 + (lane & 15)) * FS + ((lane >> 4) << 2)) * 4;

    // Q fragments: premul by scale*log2e, re-round rna (once per CTA)
    uint32_t qf[8][4];
#pragma unroll
    for (int ks = 0; ks < 8; ks++) {
        const float* q0p = Qg + base + (size_t)gr0 * DD;
        const float* q1p = Qg + base + (size_t)(gr0 + 8) * DD;
        qf[ks][0] = f2tf32(q0p[ks * 8 + lm]     * SCALE_LOG2E);
        qf[ks][1] = f2tf32(q1p[ks * 8 + lm]     * SCALE_LOG2E);
        qf[ks][2] = f2tf32(q0p[ks * 8 + lm + 4] * SCALE_LOG2E);
        qf[ks][3] = f2tf32(q1p[ks * 8 + lm + 4] * SCALE_LOG2E);
    }

    float oacc[8][4];
#pragma unroll
    for (int dt = 0; dt < 8; dt++)
#pragma unroll
        for (int r = 0; r < 4; r++) oacc[dt][r] = 0.0f;
    float m0 = -1e30f, m1 = -1e30f, l0 = 0.0f, l1 = 0.0f;

    // K/V tile register prefetch (bit copies — data already tf32)
    uint4 kr[8];
    uint32_t vr[32];
    const uint32_t* Ku = (const uint32_t*)Kg;
    const uint32_t* Vu = (const uint32_t*)Vg;
    auto load_kv = [&](int kt) {
        const int k0 = kt * 64;
#pragma unroll
        for (int i = 0; i < 8; i++) {
            int fi = tid + 128 * i;
            int row = fi >> 4;
            int c4 = (fi & 15) * 4;
            kr[i] = *(const uint4*)(Ku + base + (size_t)(k0 + row) * DD + c4);
        }
#pragma unroll
        for (int i = 0; i < 32; i++) {
            int fi = tid + 128 * i;
            int row = fi >> 6;
            int d = fi & 63;
            vr[i] = Vu[base + (size_t)(k0 + row) * DD + d];
        }
    };
    auto store_kv = [&](int buf) {
        uint32_t* Ks = sm + buf * 64 * FS;
        uint32_t* Vt = sm + (2 + buf) * 64 * FS;
#pragma unroll
        for (int i = 0; i < 8; i++) {
            int fi = tid + 128 * i;
            int row = fi >> 4;
            int c4 = (fi & 15) * 4;
            uint32_t* dst = Ks + row * FS + c4;
            dst[0] = kr[i].x; dst[1] = kr[i].y;
            dst[2] = kr[i].z; dst[3] = kr[i].w;
        }
#pragma unroll
        for (int i = 0; i < 32; i++) {
            int fi = tid + 128 * i;
            int row = fi >> 6;
            int d = fi & 63;
            Vt[d * FS + row] = vr[i];
        }
    };

    load_kv(0);
    store_kv(0);
    __syncthreads();

    const int nkt = qt + 1;
    for (int kt = 0; kt < nkt; kt++) {
        const int k0 = kt * 64;
        const int buf = kt & 1;
        const uint32_t ksBuf = smb + buf * 64 * FS * 4;
        const uint32_t vtBuf = smb + (2 + buf) * 64 * FS * 4;

        // S = (Q*scale*log2e) @ K^T
        float sf[8][4];
#pragma unroll
        for (int nt = 0; nt < 8; nt++)
#pragma unroll
            for (int r = 0; r < 4; r++) sf[nt][r] = 0.0f;

#pragma unroll
        for (int ks = 0; ks < 8; ks++) {
            const uint32_t kbB = ks * 32;
#pragma unroll
            for (int t = 0; t < 4; t++) {
                uint32_t bb[4];
                ldsm_x4(bb, ksBuf + kvOff[t] + kbB);
                mma_tf32(sf[2 * t],     qf[ks], bb[0], bb[1]);
                mma_tf32(sf[2 * t + 1], qf[ks], bb[2], bb[3]);
            }
        }

        if (kt + 1 < nkt) load_kv(kt + 1);   // hide LDG under softmax+PV

        if (k0 + 63 > q0 + wid * 16) {
#pragma unroll
            for (int nt = 0; nt < 8; nt++) {
                int c = k0 + nt * 8 + 2 * lm;
                if (c     > gr0)     sf[nt][0] = -1e30f;
                if (c + 1 > gr0)     sf[nt][1] = -1e30f;
                if (c     > gr0 + 8) sf[nt][2] = -1e30f;
                if (c + 1 > gr0 + 8) sf[nt][3] = -1e30f;
            }
        }

        // online softmax in log2 domain
        float rm0 = -1e30f, rm1 = -1e30f;
#pragma unroll
        for (int nt = 0; nt < 8; nt++) {
            rm0 = fmaxf(rm0, fmaxf(sf[nt][0], sf[nt][1]));
            rm1 = fmaxf(rm1, fmaxf(sf[nt][2], sf[nt][3]));
        }
#pragma unroll
        for (int off = 1; off <= 2; off <<= 1) {
            rm0 = fmaxf(rm0, __shfl_xor_sync(0xffffffffu, rm0, off));
            rm1 = fmaxf(rm1, __shfl_xor_sync(0xffffffffu, rm1, off));
        }
        float nm0 = fmaxf(m0, rm0), nm1 = fmaxf(m1, rm1);
        float a0 = ex2f(m0 - nm0), a1 = ex2f(m1 - nm1);
        float rs0 = 0.0f, rs1 = 0.0f;
#pragma unroll
        for (int nt = 0; nt < 8; nt++) {
            sf[nt][0] = ex2f(sf[nt][0] - nm0);
            sf[nt][1] = ex2f(sf[nt][1] - nm0);
            sf[nt][2] = ex2f(sf[nt][2] - nm1);
            sf[nt][3] = ex2f(sf[nt][3] - nm1);
            rs0 += sf[nt][0] + sf[nt][1];
            rs1 += sf[nt][2] + sf[nt][3];
        }
#pragma unroll
        for (int off = 1; off <= 2; off <<= 1) {
            rs0 += __shfl_xor_sync(0xffffffffu, rs0, off);
            rs1 += __shfl_xor_sync(0xffffffffu, rs1, off);
        }
        l0 = l0 * a0 + rs0;  m0 = nm0;
        l1 = l1 * a1 + rs1;  m1 = nm1;
#pragma unroll
        for (int dt = 0; dt < 8; dt++) {
            oacc[dt][0] *= a0; oacc[dt][1] *= a0;
            oacc[dt][2] *= a1; oacc[dt][3] *= a1;
        }

        // P -> smem (tf32), warp-private rows
#pragma unroll
        for (int nt = 0; nt < 8; nt++) {
            int c = nt * 8 + 2 * lm;
            uint32_t p0 = f2tf32(sf[nt][0]), p1 = f2tf32(sf[nt][1]);
            uint32_t p2 = f2tf32(sf[nt][2]), p3 = f2tf32(sf[nt][3]);
            *(uint2*)&Ps[prow * FS + c]       = make_uint2(p0, p1);
            *(uint2*)&Ps[(prow + 8) * FS + c] = make_uint2(p2, p3);
        }
        __syncwarp();

        // O += P @ V
#pragma unroll
        for (int ks = 0; ks < 8; ks++) {
            const uint32_t kbB = ks * 32;
            uint32_t af[4];
            ldsm_x4(af, psb + pOff + kbB);
#pragma unroll
            for (int t = 0; t < 4; t++) {
                uint32_t bb[4];
                ldsm_x4(bb, vtBuf + kvOff[t] + kbB);
                mma_tf32(oacc[2 * t],     af, bb[0], bb[1]);
                mma_tf32(oacc[2 * t + 1], af, bb[2], bb[3]);
            }
        }

        if (kt + 1 < nkt) {
            store_kv(buf ^ 1);
            __syncthreads();   // single sync per tile
        }
    }

    float inv0 = 1.0f / l0, inv1 = 1.0f / l1;
#pragma unroll
    for (int dt = 0; dt < 8; dt++) {
        int d = dt * 8 + 2 * lm;
        float2 o0 = make_float2(oacc[dt][0] * inv0, oacc[dt][1] * inv0);
        float2 o1 = make_float2(oacc[dt][2] * inv1, oacc[dt][3] * inv1);
        *(float2*)(Og + base + (size_t)gr0 * DD + d) = o0;
        *(float2*)(Og + base + (size_t)(gr0 + 8) * DD + d) = o1;
    }
}

// ---------------------------------------------------------------------------
// Launch
// ---------------------------------------------------------------------------
extern "C" void kernel_launch(void* const* d_in, const int* in_sizes, int n_in,
                              void* d_out, int out_size)
{
    const float* query = (const float*)d_in[0];
    const float* key   = (const float*)d_in[1];
    const float* value = (const float*)d_in[2];
    const float* wq = (const float*)d_in[3];
    const float* bq = (const float*)d_in[4];
    const float* wk = (const float*)d_in[5];
    const float* bk = (const float*)d_in[6];
    const float* wv = (const float*)d_in[7];
    const float* bv = (const float*)d_in[8];
    const float* wo = (const float*)d_in[9];
    const float* bo = (const float*)d_in[10];
    float* out = (float*)d_out;

    float *q_s, *k_s, *v_s, *o_s;
    uint32_t* wt;
    cudaGetSymbolAddress((void**)&q_s, g_q);
    cudaGetSymbolAddress((void**)&k_s, g_k);
    cudaGetSymbolAddress((void**)&v_s, g_v);
    cudaGetSymbolAddress((void**)&o_s, g_o);
    cudaGetSymbolAddress((void**)&wt, g_wt);

    cudaFuncSetAttribute(flash_mma_kernel,
                         cudaFuncAttributeMaxDynamicSharedMemorySize, FLASH_SMEM);

    // 0. pre-convert weights to tf32 bits (wq, wk, wv, wo)
    cvt_w_kernel<<<dim3(1024, 4), 256>>>(wq, wk, wv, wo, wt);

    // 1. fused q/k/v projections (A converted in-kernel, outputs tf32-rounded)
    dim3 gproj3(DD / 128, MROWS / 128, 3);
    gemm_mma_kernel<1><<<gproj3, 128>>>(query, key, value, wt,
                                        bq, bk, bv, q_s, k_s, v_s, 1);

    // 2. flash attention (R12 winner)
    dim3 gattn(SS / 64, HH, BB);   // (32, 16, 2) = 1024 CTAs
    flash_mma_kernel<<<gattn, 128, FLASH_SMEM>>>(q_s, k_s, v_s, o_s);

    // 3. output projection (A already tf32 bits -> bit-copy; full fp32 out)
    dim3 gproj1(DD / 128, MROWS / 128, 1);
    gemm_mma_kernel<0><<<gproj1, 128>>>(o_s, o_s, o_s, wt + 3ull * DD * DD,
                                        bo, bo, bo, out, out, out, 0);
}

// round 15
// speedup vs baseline: 1.0235x; 1.0191x over previous
#include <cuda_runtime.h>
#include <cstdint>

// Problem constants
#define BB 2
#define SS 2048
#define DD 1024
#define HH 16
#define DK 64
#define MROWS (BB * SS)   // 4096

// Scratch (static device globals — allocation-guard safe)
__device__ float g_q[MROWS * DD];
__device__ float g_k[MROWS * DD];
__device__ float g_v[MROWS * DD];
__device__ float g_o[MROWS * DD];

// ---------------------------------------------------------------------------
// Helpers
// ---------------------------------------------------------------------------
static __device__ __forceinline__ uint32_t f2tf32(float x) {
    uint32_t u;
    asm("cvt.rna.tf32.f32 %0, %1;" : "=r"(u) : "f"(x));
    return u;
}

static __device__ __forceinline__ float ex2f(float x) {
    float r;
    asm("ex2.approx.f32 %0, %1;" : "=f"(r) : "f"(x));
    return r;
}

static __device__ __forceinline__ uint32_t cvta_smem(const void* p) {
    uint32_t a;
    asm("{ .reg .u64 t; cvta.to.shared.u64 t, %1; cvt.u32.u64 %0, t; }"
        : "=r"(a) : "l"(p));
    return a;
}

static __device__ __forceinline__ void mma_tf32(float c[4], const uint32_t a[4],
                                                uint32_t b0, uint32_t b1) {
    asm volatile(
        "mma.sync.aligned.m16n8k8.row.col.f32.tf32.tf32.f32 "
        "{%0,%1,%2,%3}, {%4,%5,%6,%7}, {%8,%9}, {%0,%1,%2,%3};"
        : "+f"(c[0]), "+f"(c[1]), "+f"(c[2]), "+f"(c[3])
        : "r"(a[0]), "r"(a[1]), "r"(a[2]), "r"(a[3]), "r"(b0), "r"(b1));
}

static __device__ __forceinline__ void ldsm_x4(uint32_t r[4], uint32_t addr) {
    asm volatile("ldmatrix.sync.aligned.m8n8.x4.shared.b16 {%0,%1,%2,%3}, [%4];"
        : "=r"(r[0]), "=r"(r[1]), "=r"(r[2]), "=r"(r[3]) : "r"(addr));
}

// ---------------------------------------------------------------------------
// Fused tf32 mma.sync GEMM (R6/R12 config): C[z] = A[z] @ W[z]^T + bias[z].
// CTA 128x128, BK=16, 128 threads (4 warps of 64x64). doRound: tf32-round C.
// Scheduling tweak: next-chunk LDGs issued BEFORE the barrier.
// ---------------------------------------------------------------------------
#define BK 16
#define APAD 20
#define GBUF (128 * APAD)

__global__ __launch_bounds__(128, 2) void gemm3_mma_kernel(
    const float* __restrict__ A0, const float* __restrict__ A1, const float* __restrict__ A2,
    const float* __restrict__ W0, const float* __restrict__ W1, const float* __restrict__ W2,
    const float* __restrict__ b0p, const float* __restrict__ b1p, const float* __restrict__ b2p,
    float* __restrict__ C0, float* __restrict__ C1, float* __restrict__ C2,
    int doRound)
{
    __shared__ uint32_t As[2][GBUF];
    __shared__ uint32_t Bs[2][GBUF];

    const int z = blockIdx.z;
    const float* A = (z == 0) ? A0 : (z == 1) ? A1 : A2;
    const float* W = (z == 0) ? W0 : (z == 1) ? W1 : W2;
    const float* bias = (z == 0) ? b0p : (z == 1) ? b1p : b2p;
    float* C = (z == 0) ? C0 : (z == 1) ? C1 : C2;

    const int tid = threadIdx.x;
    const int lane = tid & 31;
    const int wid = tid >> 5;
    const int wm = wid & 1;
    const int wn = wid >> 1;
    const int l4 = lane >> 2;
    const int lm = lane & 3;
    const int rowBase = blockIdx.y * 128;
    const int colBase = blockIdx.x * 128;

    const uint32_t asb = cvta_smem(As);
    const uint32_t bsb = cvta_smem(Bs);

    uint32_t aOff[4], bOff[4];
#pragma unroll
    for (int mt = 0; mt < 4; mt++)
        aOff[mt] = ((wm * 64 + mt * 16 + (lane & 15)) * APAD + ((lane >> 4) << 2)) * 4;
#pragma unroll
    for (int t = 0; t < 4; t++)
        bOff[t] = ((wn * 64 + t * 16 + (lane & 7) + 8 * ((lane >> 4) & 1)) * APAD
                   + 4 * ((lane >> 3) & 1)) * 4;

    float acc[4][8][4];
#pragma unroll
    for (int mt = 0; mt < 4; mt++)
#pragma unroll
        for (int nt = 0; nt < 8; nt++)
#pragma unroll
            for (int r = 0; r < 4; r++) acc[mt][nt][r] = 0.0f;

    float4 ra[4], rb[4];
    auto loadg = [&](int ic) {
        const int kOff = ic * BK;
#pragma unroll
        for (int i = 0; i < 4; i++) {
            int fi = tid + 128 * i;
            int row = fi >> 2;
            int k4 = fi & 3;
            ra[i] = *(const float4*)(A + (size_t)(rowBase + row) * DD + kOff + k4 * 4);
            rb[i] = *(const float4*)(W + (size_t)(colBase + row) * DD + kOff + k4 * 4);
        }
    };

    loadg(0);
    const int nChunks = DD / BK;

    for (int ic = 0; ic < nChunks; ic++) {
        const int buf = ic & 1;
        const uint32_t bufB = buf * (GBUF * 4);
#pragma unroll
        for (int i = 0; i < 4; i++) {
            int fi = tid + 128 * i;
            int row = fi >> 2;
            int k4 = fi & 3;
            uint32_t* da = &As[buf][row * APAD + k4 * 4];
            da[0] = f2tf32(ra[i].x); da[1] = f2tf32(ra[i].y);
            da[2] = f2tf32(ra[i].z); da[3] = f2tf32(ra[i].w);
            uint32_t* db = &Bs[buf][row * APAD + k4 * 4];
            db[0] = f2tf32(rb[i].x); db[1] = f2tf32(rb[i].y);
            db[2] = f2tf32(rb[i].z); db[3] = f2tf32(rb[i].w);
        }
        // issue next chunk's LDGs before the barrier: they fly during the
        // barrier wait and the MMA phase (registers ra/rb already consumed)
        if (ic + 1 < nChunks) loadg(ic + 1);
        __syncthreads();

#pragma unroll
        for (int ks = 0; ks < 2; ks++) {
            const uint32_t kbB = ks * 32;
            uint32_t af[4][4];
#pragma unroll
            for (int mt = 0; mt < 4; mt++)
                ldsm_x4(af[mt], asb + bufB + aOff[mt] + kbB);
#pragma unroll
            for (int t = 0; t < 4; t++) {
                uint32_t bb[4];
                ldsm_x4(bb, bsb + bufB + bOff[t] + kbB);
#pragma unroll
                for (int mt = 0; mt < 4; mt++) {
                    mma_tf32(acc[mt][2 * t],     af[mt], bb[0], bb[1]);
                    mma_tf32(acc[mt][2 * t + 1], af[mt], bb[2], bb[3]);
                }
            }
        }
        // no trailing sync: double-buffered smem
    }

#pragma unroll
    for (int nt = 0; nt < 8; nt++) {
        int c = colBase + wn * 64 + nt * 8 + 2 * lm;
        float2 bv = *(const float2*)(bias + c);
#pragma unroll
        for (int mt = 0; mt < 4; mt++) {
            int r = rowBase + wm * 64 + mt * 16 + l4;
            float2 o0 = make_float2(acc[mt][nt][0] + bv.x, acc[mt][nt][1] + bv.y);
            float2 o1 = make_float2(acc[mt][nt][2] + bv.x, acc[mt][nt][3] + bv.y);
            if (doRound) {
                o0.x = __uint_as_float(f2tf32(o0.x)); o0.y = __uint_as_float(f2tf32(o0.y));
                o1.x = __uint_as_float(f2tf32(o1.x)); o1.y = __uint_as_float(f2tf32(o1.y));
            }
            *(float2*)(C + (size_t)r * DD + c) = o0;
            *(float2*)(C + (size_t)(r + 8) * DD + c) = o1;
        }
    }
}

// ---------------------------------------------------------------------------
// Flash attention (causal) — R12 winner + LDG hoist: load_kv(kt+1) issues
// BEFORE the S-MMA loop so global loads overlap the MMAs too.
// 128 threads (4 warps x 16 q-rows), 64 q-rows/CTA, 64-key tiles,
// double-buffered K/V smem, single sync per tile, bit-copy staging
// (inputs pre-rounded tf32), log2-domain softmax.
// ---------------------------------------------------------------------------
#define FS 68
#define FLASH_SMEM ((4 * 64 + 64) * FS * 4)   // 87040 B
#define SCALE_LOG2E 0.180336880f              // 0.125 * log2(e)

__global__ __launch_bounds__(128, 2) void flash_mma_kernel(
    const float* __restrict__ Qg, const float* __restrict__ Kg,
    const float* __restrict__ Vg, float* __restrict__ Og)
{
    extern __shared__ uint32_t sm[];
    uint32_t* Ps = sm + 4 * 64 * FS;   // [64][FS]

    const int tid = threadIdx.x;
    const int lane = tid & 31;
    const int wid = tid >> 5;          // 0..3
    const int l4 = lane >> 2;
    const int lm = lane & 3;

    const int qt = (gridDim.x - 1) - blockIdx.x;   // heavy tiles first
    const int h  = blockIdx.y;
    const int b  = blockIdx.z;
    const int q0 = qt * 64;

    const size_t base = (size_t)b * SS * DD + (size_t)h * DK;

    const int gr0 = q0 + wid * 16 + l4;
    const int prow = wid * 16 + l4;

    const uint32_t smb = cvta_smem(sm);
    const uint32_t psb = smb + 4 * 64 * FS * 4;

    uint32_t kvOff[4];
#pragma unroll
    for (int t = 0; t < 4; t++)
        kvOff[t] = ((t * 16 + (lane & 7) + 8 * ((lane >> 4) & 1)) * FS
                    + 4 * ((lane >> 3) & 1)) * 4;
    const uint32_t pOff = ((wid * 16 + (lane & 15)) * FS + ((lane >> 4) << 2)) * 4;

    // Q fragments: premul by scale*log2e, re-round rna (once per CTA)
    uint32_t qf[8][4];
#pragma unroll
    for (int ks = 0; ks < 8; ks++) {
        const float* q0p = Qg + base + (size_t)gr0 * DD;
        const float* q1p = Qg + base + (size_t)(gr0 + 8) * DD;
        qf[ks][0] = f2tf32(q0p[ks * 8 + lm]     * SCALE_LOG2E);
        qf[ks][1] = f2tf32(q1p[ks * 8 + lm]     * SCALE_LOG2E);
        qf[ks][2] = f2tf32(q0p[ks * 8 + lm + 4] * SCALE_LOG2E);
        qf[ks][3] = f2tf32(q1p[ks * 8 + lm + 4] * SCALE_LOG2E);
    }

    float oacc[8][4];
#pragma unroll
    for (int dt = 0; dt < 8; dt++)
#pragma unroll
        for (int r = 0; r < 4; r++) oacc[dt][r] = 0.0f;
    float m0 = -1e30f, m1 = -1e30f, l0 = 0.0f, l1 = 0.0f;

    // K/V tile register prefetch (bit copies — data already tf32)
    uint4 kr[8];
    uint32_t vr[32];
    const uint32_t* Ku = (const uint32_t*)Kg;
    const uint32_t* Vu = (const uint32_t*)Vg;
    auto load_kv = [&](int kt) {
        const int k0 = kt * 64;
#pragma unroll
        for (int i = 0; i < 8; i++) {
            int fi = tid + 128 * i;
            int row = fi >> 4;
            int c4 = (fi & 15) * 4;
            kr[i] = *(const uint4*)(Ku + base + (size_t)(k0 + row) * DD + c4);
        }
#pragma unroll
        for (int i = 0; i < 32; i++) {
            int fi = tid + 128 * i;
            int row = fi >> 6;
            int d = fi & 63;
            vr[i] = Vu[base + (size_t)(k0 + row) * DD + d];
        }
    };
    auto store_kv = [&](int buf) {
        uint32_t* Ks = sm + buf * 64 * FS;
        uint32_t* Vt = sm + (2 + buf) * 64 * FS;
#pragma unroll
        for (int i = 0; i < 8; i++) {
            int fi = tid + 128 * i;
            int row = fi >> 4;
            int c4 = (fi & 15) * 4;
            uint32_t* dst = Ks + row * FS + c4;
            dst[0] = kr[i].x; dst[1] = kr[i].y;
            dst[2] = kr[i].z; dst[3] = kr[i].w;
        }
#pragma unroll
        for (int i = 0; i < 32; i++) {
            int fi = tid + 128 * i;
            int row = fi >> 6;
            int d = fi & 63;
            Vt[d * FS + row] = vr[i];
        }
    };

    load_kv(0);
    store_kv(0);
    __syncthreads();

    const int nkt = qt + 1;
    for (int kt = 0; kt < nkt; kt++) {
        const int k0 = kt * 64;
        const int buf = kt & 1;
        const uint32_t ksBuf = smb + buf * 64 * FS * 4;
        const uint32_t vtBuf = smb + (2 + buf) * 64 * FS * 4;

        // hoist: next tile's LDGs fly across S-MMA + softmax + PV
        if (kt + 1 < nkt) load_kv(kt + 1);

        // S = (Q*scale*log2e) @ K^T
        float sf[8][4];
#pragma unroll
        for (int nt = 0; nt < 8; nt++)
#pragma unroll
            for (int r = 0; r < 4; r++) sf[nt][r] = 0.0f;

#pragma unroll
        for (int ks = 0; ks < 8; ks++) {
            const uint32_t kbB = ks * 32;
#pragma unroll
            for (int t = 0; t < 4; t++) {
                uint32_t bb[4];
                ldsm_x4(bb, ksBuf + kvOff[t] + kbB);
                mma_tf32(sf[2 * t],     qf[ks], bb[0], bb[1]);
                mma_tf32(sf[2 * t + 1], qf[ks], bb[2], bb[3]);
            }
        }

        if (k0 + 63 > q0 + wid * 16) {
#pragma unroll
            for (int nt = 0; nt < 8; nt++) {
                int c = k0 + nt * 8 + 2 * lm;
                if (c     > gr0)     sf[nt][0] = -1e30f;
                if (c + 1 > gr0)     sf[nt][1] = -1e30f;
                if (c     > gr0 + 8) sf[nt][2] = -1e30f;
                if (c + 1 > gr0 + 8) sf[nt][3] = -1e30f;
            }
        }

        // online softmax in log2 domain
        float rm0 = -1e30f, rm1 = -1e30f;
#pragma unroll
        for (int nt = 0; nt < 8; nt++) {
            rm0 = fmaxf(rm0, fmaxf(sf[nt][0], sf[nt][1]));
            rm1 = fmaxf(rm1, fmaxf(sf[nt][2], sf[nt][3]));
        }
#pragma unroll
        for (int off = 1; off <= 2; off <<= 1) {
            rm0 = fmaxf(rm0, __shfl_xor_sync(0xffffffffu, rm0, off));
            rm1 = fmaxf(rm1, __shfl_xor_sync(0xffffffffu, rm1, off));
        }
        float nm0 = fmaxf(m0, rm0), nm1 = fmaxf(m1, rm1);
        float a0 = ex2f(m0 - nm0), a1 = ex2f(m1 - nm1);
        float rs0 = 0.0f, rs1 = 0.0f;
#pragma unroll
        for (int nt = 0; nt < 8; nt++) {
            sf[nt][0] = ex2f(sf[nt][0] - nm0);
            sf[nt][1] = ex2f(sf[nt][1] - nm0);
            sf[nt][2] = ex2f(sf[nt][2] - nm1);
            sf[nt][3] = ex2f(sf[nt][3] - nm1);
            rs0 += sf[nt][0] + sf[nt][1];
            rs1 += sf[nt][2] + sf[nt][3];
        }
#pragma unroll
        for (int off = 1; off <= 2; off <<= 1) {
            rs0 += __shfl_xor_sync(0xffffffffu, rs0, off);
            rs1 += __shfl_xor_sync(0xffffffffu, rs1, off);
        }
        l0 = l0 * a0 + rs0;  m0 = nm0;
        l1 = l1 * a1 + rs1;  m1 = nm1;
#pragma unroll
        for (int dt = 0; dt < 8; dt++) {
            oacc[dt][0] *= a0; oacc[dt][1] *= a0;
            oacc[dt][2] *= a1; oacc[dt][3] *= a1;
        }

        // P -> smem (tf32), warp-private rows
#pragma unroll
        for (int nt = 0; nt < 8; nt++) {
            int c = nt * 8 + 2 * lm;
            uint32_t p0 = f2tf32(sf[nt][0]), p1 = f2tf32(sf[nt][1]);
            uint32_t p2 = f2tf32(sf[nt][2]), p3 = f2tf32(sf[nt][3]);
            *(uint2*)&Ps[prow * FS + c]       = make_uint2(p0, p1);
            *(uint2*)&Ps[(prow + 8) * FS + c] = make_uint2(p2, p3);
        }
        __syncwarp();

        // O += P @ V
#pragma unroll
        for (int ks = 0; ks < 8; ks++) {
            const uint32_t kbB = ks * 32;
            uint32_t af[4];
            ldsm_x4(af, psb + pOff + kbB);
#pragma unroll
            for (int t = 0; t < 4; t++) {
                uint32_t bb[4];
                ldsm_x4(bb, vtBuf + kvOff[t] + kbB);
                mma_tf32(oacc[2 * t],     af, bb[0], bb[1]);
                mma_tf32(oacc[2 * t + 1], af, bb[2], bb[3]);
            }
        }

        if (kt + 1 < nkt) {
            store_kv(buf ^ 1);
            __syncthreads();   // single sync per tile
        }
    }

    float inv0 = 1.0f / l0, inv1 = 1.0f / l1;
#pragma unroll
    for (int dt = 0; dt < 8; dt++) {
        int d = dt * 8 + 2 * lm;
        float2 o0 = make_float2(oacc[dt][0] * inv0, oacc[dt][1] * inv0);
        float2 o1 = make_float2(oacc[dt][2] * inv1, oacc[dt][3] * inv1);
        *(float2*)(Og + base + (size_t)gr0 * DD + d) = o0;
        *(float2*)(Og + base + (size_t)(gr0 + 8) * DD + d) = o1;
    }
}

// ---------------------------------------------------------------------------
// Launch
// ---------------------------------------------------------------------------
extern "C" void kernel_launch(void* const* d_in, const int* in_sizes, int n_in,
                              void* d_out, int out_size)
{
    const float* query = (const float*)d_in[0];
    const float* key   = (const float*)d_in[1];
    const float* value = (const float*)d_in[2];
    const float* wq = (const float*)d_in[3];
    const float* bq = (const float*)d_in[4];
    const float* wk = (const float*)d_in[5];
    const float* bk = (const float*)d_in[6];
    const float* wv = (const float*)d_in[7];
    const float* bv = (const float*)d_in[8];
    const float* wo = (const float*)d_in[9];
    const float* bo = (const float*)d_in[10];
    float* out = (float*)d_out;

    float *q_s, *k_s, *v_s, *o_s;
    cudaGetSymbolAddress((void**)&q_s, g_q);
    cudaGetSymbolAddress((void**)&k_s, g_k);
    cudaGetSymbolAddress((void**)&v_s, g_v);
    cudaGetSymbolAddress((void**)&o_s, g_o);

    cudaFuncSetAttribute(flash_mma_kernel,
                         cudaFuncAttributeMaxDynamicSharedMemorySize, FLASH_SMEM);

    // 1. fused q/k/v projections (outputs tf32-rounded)
    dim3 gproj3(DD / 128, MROWS / 128, 3);
    gemm3_mma_kernel<<<gproj3, 128>>>(query, key, value, wq, wk, wv,
                                      bq, bk, bv, q_s, k_s, v_s, 1);

    // 2. flash attention (R12 winner + LDG hoist)
    dim3 gattn(SS / 64, HH, BB);   // (32, 16, 2) = 1024 CTAs
    flash_mma_kernel<<<gattn, 128, FLASH_SMEM>>>(q_s, k_s, v_s, o_s);

    // 3. output projection (full fp32 output)
    dim3 gproj1(DD / 128, MROWS / 128, 1);
    gemm3_mma_kernel<<<gproj1, 128>>>(o_s, o_s, o_s, wo, wo, wo,
                                      bo, bo, bo, out, out, out, 0);
}

// round 16
// speedup vs baseline: 1.2035x; 1.1759x over previous
#include <cuda_runtime.h>
#include <cstdint>

// Problem constants
#define BB 2
#define SS 2048
#define DD 1024
#define HH 16
#define DK 64
#define MROWS (BB * SS)   // 4096

// Scratch (static device globals — allocation-guard safe)
__device__ float g_q[MROWS * DD];
__device__ float g_k[MROWS * DD];
__device__ float g_v[MROWS * DD];
__device__ float g_o[MROWS * DD];

// ---------------------------------------------------------------------------
// Helpers
// ---------------------------------------------------------------------------
static __device__ __forceinline__ uint32_t f2tf32(float x) {
    uint32_t u;
    asm("cvt.rna.tf32.f32 %0, %1;" : "=r"(u) : "f"(x));
    return u;
}

static __device__ __forceinline__ uint32_t h2pack(float lo, float hi) {
    uint32_t r;
    asm("cvt.rn.f16x2.f32 %0, %1, %2;" : "=r"(r) : "f"(hi), "f"(lo));
    return r;
}

static __device__ __forceinline__ float ex2f(float x) {
    float r;
    asm("ex2.approx.f32 %0, %1;" : "=f"(r) : "f"(x));
    return r;
}

static __device__ __forceinline__ uint32_t cvta_smem(const void* p) {
    uint32_t a;
    asm("{ .reg .u64 t; cvta.to.shared.u64 t, %1; cvt.u32.u64 %0, t; }"
        : "=r"(a) : "l"(p));
    return a;
}

// tf32 m16n8k8 (flash)
static __device__ __forceinline__ void mma_tf32(float c[4], const uint32_t a[4],
                                                uint32_t b0, uint32_t b1) {
    asm volatile(
        "mma.sync.aligned.m16n8k8.row.col.f32.tf32.tf32.f32 "
        "{%0,%1,%2,%3}, {%4,%5,%6,%7}, {%8,%9}, {%0,%1,%2,%3};"
        : "+f"(c[0]), "+f"(c[1]), "+f"(c[2]), "+f"(c[3])
        : "r"(a[0]), "r"(a[1]), "r"(a[2]), "r"(a[3]), "r"(b0), "r"(b1));
}

// fp16 m16n8k16 (GEMMs) — fp32 accumulate
static __device__ __forceinline__ void mma_f16(float c[4], const uint32_t a[4],
                                               uint32_t b0, uint32_t b1) {
    asm volatile(
        "mma.sync.aligned.m16n8k16.row.col.f32.f16.f16.f32 "
        "{%0,%1,%2,%3}, {%4,%5,%6,%7}, {%8,%9}, {%0,%1,%2,%3};"
        : "+f"(c[0]), "+f"(c[1]), "+f"(c[2]), "+f"(c[3])
        : "r"(a[0]), "r"(a[1]), "r"(a[2]), "r"(a[3]), "r"(b0), "r"(b1));
}

static __device__ __forceinline__ void ldsm_x4(uint32_t r[4], uint32_t addr) {
    asm volatile("ldmatrix.sync.aligned.m8n8.x4.shared.b16 {%0,%1,%2,%3}, [%4];"
        : "=r"(r[0]), "=r"(r[1]), "=r"(r[2]), "=r"(r[3]) : "r"(addr));
}

// ---------------------------------------------------------------------------
// Fused fp16 mma.sync GEMM: C[z] = A[z] @ W[z]^T + bias[z].
// CTA 128x128, BK=16 (k-halves), 128 threads (4 warps of 64x64).
// Smem: 32B rows (16 halves), swizzle chunk ^= (row>>2)&1 -> conflict-free
// ldsm octets. fp16 operands (same 11-bit mantissa as tf32), fp32 accum.
// Loop structure identical to the R12 winner. doRound: tf32-round outputs.
// ---------------------------------------------------------------------------
#define BK 16
#define HBUF 1024   // words per matrix per buffer (128 rows * 32B)

__global__ __launch_bounds__(128, 2) void gemm3_f16_kernel(
    const float* __restrict__ A0, const float* __restrict__ A1, const float* __restrict__ A2,
    const float* __restrict__ W0, const float* __restrict__ W1, const float* __restrict__ W2,
    const float* __restrict__ b0p, const float* __restrict__ b1p, const float* __restrict__ b2p,
    float* __restrict__ C0, float* __restrict__ C1, float* __restrict__ C2,
    int doRound)
{
    __shared__ uint32_t As[2][HBUF];
    __shared__ uint32_t Bs[2][HBUF];

    const int z = blockIdx.z;
    const float* A = (z == 0) ? A0 : (z == 1) ? A1 : A2;
    const float* W = (z == 0) ? W0 : (z == 1) ? W1 : W2;
    const float* bias = (z == 0) ? b0p : (z == 1) ? b1p : b2p;
    float* C = (z == 0) ? C0 : (z == 1) ? C1 : C2;

    const int tid = threadIdx.x;
    const int lane = tid & 31;
    const int wid = tid >> 5;
    const int wm = wid & 1;
    const int wn = wid >> 1;
    const int l4 = lane >> 2;
    const int lm = lane & 3;
    const int rowBase = blockIdx.y * 128;
    const int colBase = blockIdx.x * 128;

    const uint32_t asb = cvta_smem(As);
    const uint32_t bsb = cvta_smem(Bs);

    // ldsm fragment addresses (bytes within a buffer), 32B swizzled rows
    uint32_t aOff[4], bOff[4];
#pragma unroll
    for (int mt = 0; mt < 4; mt++) {
        uint32_t r = wm * 64 + mt * 16 + (lane & 15);
        uint32_t ck = lane >> 4;                 // 16B chunk (k-half)
        aOff[mt] = r * 32 + ((ck ^ ((r >> 2) & 1)) << 4);
    }
#pragma unroll
    for (int t = 0; t < 4; t++) {
        uint32_t r = wn * 64 + t * 16 + (lane & 7) + 8 * ((lane >> 4) & 1);
        uint32_t ck = (lane >> 3) & 1;
        bOff[t] = r * 32 + ((ck ^ ((r >> 2) & 1)) << 4);
    }

    float acc[4][8][4];
#pragma unroll
    for (int mt = 0; mt < 4; mt++)
#pragma unroll
        for (int nt = 0; nt < 8; nt++)
#pragma unroll
            for (int r = 0; r < 4; r++) acc[mt][nt][r] = 0.0f;

    float4 ra[4], rb[4];
    auto loadg = [&](int ic) {
        const int kOff = ic * BK;
#pragma unroll
        for (int i = 0; i < 4; i++) {
            int fi = tid + 128 * i;
            int row = fi >> 2;
            int q4 = fi & 3;
            ra[i] = *(const float4*)(A + (size_t)(rowBase + row) * DD + kOff + q4 * 4);
            rb[i] = *(const float4*)(W + (size_t)(colBase + row) * DD + kOff + q4 * 4);
        }
    };

    loadg(0);
    const int nChunks = DD / BK;   // 64

    for (int ic = 0; ic < nChunks; ic++) {
        const int buf = ic & 1;
        const uint32_t bufB = buf * (HBUF * 4);
#pragma unroll
        for (int i = 0; i < 4; i++) {
            int fi = tid + 128 * i;
            uint32_t row = fi >> 2;
            uint32_t q4 = fi & 3;
            uint32_t byteOff = row * 32
                + ((((q4 >> 1) ^ ((row >> 2) & 1))) << 4) + (q4 & 1) * 8;
            uint32_t a0 = h2pack(ra[i].x, ra[i].y);
            uint32_t a1 = h2pack(ra[i].z, ra[i].w);
            asm volatile("st.shared.v2.b32 [%0], {%1,%2};"
                :: "r"(asb + bufB + byteOff), "r"(a0), "r"(a1) : "memory");
            uint32_t b0 = h2pack(rb[i].x, rb[i].y);
            uint32_t b1 = h2pack(rb[i].z, rb[i].w);
            asm volatile("st.shared.v2.b32 [%0], {%1,%2};"
                :: "r"(bsb + bufB + byteOff), "r"(b0), "r"(b1) : "memory");
        }
        __syncthreads();

        if (ic + 1 < nChunks) loadg(ic + 1);

        // one k16 slice per chunk: 8 ldsm feed 32 m16n8k16 MMAs per warp
        {
            uint32_t af[4][4];
#pragma unroll
            for (int mt = 0; mt < 4; mt++)
                ldsm_x4(af[mt], asb + bufB + aOff[mt]);
#pragma unroll
            for (int t = 0; t < 4; t++) {
                uint32_t bb[4];
                ldsm_x4(bb, bsb + bufB + bOff[t]);
#pragma unroll
                for (int mt = 0; mt < 4; mt++) {
                    mma_f16(acc[mt][2 * t],     af[mt], bb[0], bb[1]);
                    mma_f16(acc[mt][2 * t + 1], af[mt], bb[2], bb[3]);
                }
            }
        }
        // no trailing sync: double-buffered smem
    }

#pragma unroll
    for (int nt = 0; nt < 8; nt++) {
        int c = colBase + wn * 64 + nt * 8 + 2 * lm;
        float2 bv = *(const float2*)(bias + c);
#pragma unroll
        for (int mt = 0; mt < 4; mt++) {
            int r = rowBase + wm * 64 + mt * 16 + l4;
            float2 o0 = make_float2(acc[mt][nt][0] + bv.x, acc[mt][nt][1] + bv.y);
            float2 o1 = make_float2(acc[mt][nt][2] + bv.x, acc[mt][nt][3] + bv.y);
            if (doRound) {
                o0.x = __uint_as_float(f2tf32(o0.x)); o0.y = __uint_as_float(f2tf32(o0.y));
                o1.x = __uint_as_float(f2tf32(o1.x)); o1.y = __uint_as_float(f2tf32(o1.y));
            }
            *(float2*)(C + (size_t)r * DD + c) = o0;
            *(float2*)(C + (size_t)(r + 8) * DD + c) = o1;
        }
    }
}

// ---------------------------------------------------------------------------
// Flash attention (causal) — exact R12 winner (best: 458.6us): tf32 mma.sync,
// 128 threads (4 warps x 16 q-rows), 64 q-rows/CTA, 64-key tiles,
// double-buffered K/V smem, single sync per tile, bit-copy staging
// (inputs pre-rounded tf32), log2-domain softmax.
// ---------------------------------------------------------------------------
#define FS 68
#define FLASH_SMEM ((4 * 64 + 64) * FS * 4)   // 87040 B
#define SCALE_LOG2E 0.180336880f              // 0.125 * log2(e)

__global__ __launch_bounds__(128, 2) void flash_mma_kernel(
    const float* __restrict__ Qg, const float* __restrict__ Kg,
    const float* __restrict__ Vg, float* __restrict__ Og)
{
    extern __shared__ uint32_t sm[];
    uint32_t* Ps = sm + 4 * 64 * FS;   // [64][FS]

    const int tid = threadIdx.x;
    const int lane = tid & 31;
    const int wid = tid >> 5;          // 0..3
    const int l4 = lane >> 2;
    const int lm = lane & 3;

    const int qt = (gridDim.x - 1) - blockIdx.x;   // heavy tiles first
    const int h  = blockIdx.y;
    const int b  = blockIdx.z;
    const int q0 = qt * 64;

    const size_t base = (size_t)b * SS * DD + (size_t)h * DK;

    const int gr0 = q0 + wid * 16 + l4;
    const int prow = wid * 16 + l4;

    const uint32_t smb = cvta_smem(sm);
    const uint32_t psb = smb + 4 * 64 * FS * 4;

    uint32_t kvOff[4];
#pragma unroll
    for (int t = 0; t < 4; t++)
        kvOff[t] = ((t * 16 + (lane & 7) + 8 * ((lane >> 4) & 1)) * FS
                    + 4 * ((lane >> 3) & 1)) * 4;
    const uint32_t pOff = ((wid * 16 + (lane & 15)) * FS + ((lane >> 4) << 2)) * 4;

    // Q fragments: premul by scale*log2e, re-round rna (once per CTA)
    uint32_t qf[8][4];
#pragma unroll
    for (int ks = 0; ks < 8; ks++) {
        const float* q0p = Qg + base + (size_t)gr0 * DD;
        const float* q1p = Qg + base + (size_t)(gr0 + 8) * DD;
        qf[ks][0] = f2tf32(q0p[ks * 8 + lm]     * SCALE_LOG2E);
        qf[ks][1] = f2tf32(q1p[ks * 8 + lm]     * SCALE_LOG2E);
        qf[ks][2] = f2tf32(q0p[ks * 8 + lm + 4] * SCALE_LOG2E);
        qf[ks][3] = f2tf32(q1p[ks * 8 + lm + 4] * SCALE_LOG2E);
    }

    float oacc[8][4];
#pragma unroll
    for (int dt = 0; dt < 8; dt++)
#pragma unroll
        for (int r = 0; r < 4; r++) oacc[dt][r] = 0.0f;
    float m0 = -1e30f, m1 = -1e30f, l0 = 0.0f, l1 = 0.0f;

    // K/V tile register prefetch (bit copies — data already tf32)
    uint4 kr[8];
    uint32_t vr[32];
    const uint32_t* Ku = (const uint32_t*)Kg;
    const uint32_t* Vu = (const uint32_t*)Vg;
    auto load_kv = [&](int kt) {
        const int k0 = kt * 64;
#pragma unroll
        for (int i = 0; i < 8; i++) {
            int fi = tid + 128 * i;
            int row = fi >> 4;
            int c4 = (fi & 15) * 4;
            kr[i] = *(const uint4*)(Ku + base + (size_t)(k0 + row) * DD + c4);
        }
#pragma unroll
        for (int i = 0; i < 32; i++) {
            int fi = tid + 128 * i;
            int row = fi >> 6;
            int d = fi & 63;
            vr[i] = Vu[base + (size_t)(k0 + row) * DD + d];
        }
    };
    auto store_kv = [&](int buf) {
        uint32_t* Ks = sm + buf * 64 * FS;
        uint32_t* Vt = sm + (2 + buf) * 64 * FS;
#pragma unroll
        for (int i = 0; i < 8; i++) {
            int fi = tid + 128 * i;
            int row = fi >> 4;
            int c4 = (fi & 15) * 4;
            uint32_t* dst = Ks + row * FS + c4;
            dst[0] = kr[i].x; dst[1] = kr[i].y;
            dst[2] = kr[i].z; dst[3] = kr[i].w;
        }
#pragma unroll
        for (int i = 0; i < 32; i++) {
            int fi = tid + 128 * i;
            int row = fi >> 6;
            int d = fi & 63;
            Vt[d * FS + row] = vr[i];
        }
    };

    load_kv(0);
    store_kv(0);
    __syncthreads();

    const int nkt = qt + 1;
    for (int kt = 0; kt < nkt; kt++) {
        const int k0 = kt * 64;
        const int buf = kt & 1;
        const uint32_t ksBuf = smb + buf * 64 * FS * 4;
        const uint32_t vtBuf = smb + (2 + buf) * 64 * FS * 4;

        // S = (Q*scale*log2e) @ K^T
        float sf[8][4];
#pragma unroll
        for (int nt = 0; nt < 8; nt++)
#pragma unroll
            for (int r = 0; r < 4; r++) sf[nt][r] = 0.0f;

#pragma unroll
        for (int ks = 0; ks < 8; ks++) {
            const uint32_t kbB = ks * 32;
#pragma unroll
            for (int t = 0; t < 4; t++) {
                uint32_t bb[4];
                ldsm_x4(bb, ksBuf + kvOff[t] + kbB);
                mma_tf32(sf[2 * t],     qf[ks], bb[0], bb[1]);
                mma_tf32(sf[2 * t + 1], qf[ks], bb[2], bb[3]);
            }
        }

        if (kt + 1 < nkt) load_kv(kt + 1);   // hide LDG under softmax+PV

        if (k0 + 63 > q0 + wid * 16) {
#pragma unroll
            for (int nt = 0; nt < 8; nt++) {
                int c = k0 + nt * 8 + 2 * lm;
                if (c     > gr0)     sf[nt][0] = -1e30f;
                if (c + 1 > gr0)     sf[nt][1] = -1e30f;
                if (c     > gr0 + 8) sf[nt][2] = -1e30f;
                if (c + 1 > gr0 + 8) sf[nt][3] = -1e30f;
            }
        }

        // online softmax in log2 domain
        float rm0 = -1e30f, rm1 = -1e30f;
#pragma unroll
        for (int nt = 0; nt < 8; nt++) {
            rm0 = fmaxf(rm0, fmaxf(sf[nt][0], sf[nt][1]));
            rm1 = fmaxf(rm1, fmaxf(sf[nt][2], sf[nt][3]));
        }
#pragma unroll
        for (int off = 1; off <= 2; off <<= 1) {
            rm0 = fmaxf(rm0, __shfl_xor_sync(0xffffffffu, rm0, off));
            rm1 = fmaxf(rm1, __shfl_xor_sync(0xffffffffu, rm1, off));
        }
        float nm0 = fmaxf(m0, rm0), nm1 = fmaxf(m1, rm1);
        float a0 = ex2f(m0 - nm0), a1 = ex2f(m1 - nm1);
        float rs0 = 0.0f, rs1 = 0.0f;
#pragma unroll
        for (int nt = 0; nt < 8; nt++) {
            sf[nt][0] = ex2f(sf[nt][0] - nm0);
            sf[nt][1] = ex2f(sf[nt][1] - nm0);
            sf[nt][2] = ex2f(sf[nt][2] - nm1);
            sf[nt][3] = ex2f(sf[nt][3] - nm1);
            rs0 += sf[nt][0] + sf[nt][1];
            rs1 += sf[nt][2] + sf[nt][3];
        }
#pragma unroll
        for (int off = 1; off <= 2; off <<= 1) {
            rs0 += __shfl_xor_sync(0xffffffffu, rs0, off);
            rs1 += __shfl_xor_sync(0xffffffffu, rs1, off);
        }
        l0 = l0 * a0 + rs0;  m0 = nm0;
        l1 = l1 * a1 + rs1;  m1 = nm1;
#pragma unroll
        for (int dt = 0; dt < 8; dt++) {
            oacc[dt][0] *= a0; oacc[dt][1] *= a0;
            oacc[dt][2] *= a1; oacc[dt][3] *= a1;
        }

        // P -> smem (tf32), warp-private rows
#pragma unroll
        for (int nt = 0; nt < 8; nt++) {
            int c = nt * 8 + 2 * lm;
            uint32_t p0 = f2tf32(sf[nt][0]), p1 = f2tf32(sf[nt][1]);
            uint32_t p2 = f2tf32(sf[nt][2]), p3 = f2tf32(sf[nt][3]);
            *(uint2*)&Ps[prow * FS + c]       = make_uint2(p0, p1);
            *(uint2*)&Ps[(prow + 8) * FS + c] = make_uint2(p2, p3);
        }
        __syncwarp();

        // O += P @ V
#pragma unroll
        for (int ks = 0; ks < 8; ks++) {
            const uint32_t kbB = ks * 32;
            uint32_t af[4];
            ldsm_x4(af, psb + pOff + kbB);
#pragma unroll
            for (int t = 0; t < 4; t++) {
                uint32_t bb[4];
                ldsm_x4(bb, vtBuf + kvOff[t] + kbB);
                mma_tf32(oacc[2 * t],     af, bb[0], bb[1]);
                mma_tf32(oacc[2 * t + 1], af, bb[2], bb[3]);
            }
        }

        if (kt + 1 < nkt) {
            store_kv(buf ^ 1);
            __syncthreads();   // single sync per tile
        }
    }

    float inv0 = 1.0f / l0, inv1 = 1.0f / l1;
#pragma unroll
    for (int dt = 0; dt < 8; dt++) {
        int d = dt * 8 + 2 * lm;
        float2 o0 = make_float2(oacc[dt][0] * inv0, oacc[dt][1] * inv0);
        float2 o1 = make_float2(oacc[dt][2] * inv1, oacc[dt][3] * inv1);
        *(float2*)(Og + base + (size_t)gr0 * DD + d) = o0;
        *(float2*)(Og + base + (size_t)(gr0 + 8) * DD + d) = o1;
    }
}

// ---------------------------------------------------------------------------
// Launch
// ---------------------------------------------------------------------------
extern "C" void kernel_launch(void* const* d_in, const int* in_sizes, int n_in,
                              void* d_out, int out_size)
{
    const float* query = (const float*)d_in[0];
    const float* key   = (const float*)d_in[1];
    const float* value = (const float*)d_in[2];
    const float* wq = (const float*)d_in[3];
    const float* bq = (const float*)d_in[4];
    const float* wk = (const float*)d_in[5];
    const float* bk = (const float*)d_in[6];
    const float* wv = (const float*)d_in[7];
    const float* bv = (const float*)d_in[8];
    const float* wo = (const float*)d_in[9];
    const float* bo = (const float*)d_in[10];
    float* out = (float*)d_out;

    float *q_s, *k_s, *v_s, *o_s;
    cudaGetSymbolAddress((void**)&q_s, g_q);
    cudaGetSymbolAddress((void**)&k_s, g_k);
    cudaGetSymbolAddress((void**)&v_s, g_v);
    cudaGetSymbolAddress((void**)&o_s, g_o);

    cudaFuncSetAttribute(flash_mma_kernel,
                         cudaFuncAttributeMaxDynamicSharedMemorySize, FLASH_SMEM);

    // 1. fused q/k/v projections (fp16 MMA, outputs tf32-rounded)
    dim3 gproj3(DD / 128, MROWS / 128, 3);
    gemm3_f16_kernel<<<gproj3, 128>>>(query, key, value, wq, wk, wv,
                                      bq, bk, bv, q_s, k_s, v_s, 1);

    // 2. flash attention (exact R12 winner, tf32)
    dim3 gattn(SS / 64, HH, BB);   // (32, 16, 2) = 1024 CTAs
    flash_mma_kernel<<<gattn, 128, FLASH_SMEM>>>(q_s, k_s, v_s, o_s);

    // 3. output projection (fp16 MMA, full fp32 output)
    dim3 gproj1(DD / 128, MROWS / 128, 1);
    gemm3_f16_kernel<<<gproj1, 128>>>(o_s, o_s, o_s, wo, wo, wo,
                                      bo, bo, bo, out, out, out, 0);
}

// round 17
// speedup vs baseline: 1.7686x; 1.4695x over previous
#include <cuda_runtime.h>
#include <cstdint>

// Problem constants
#define BB 2
#define SS 2048
#define DD 1024
#define HH 16
#define DK 64
#define MROWS (BB * SS)   // 4096

// Scratch (static device globals — allocation-guard safe)
// q/k/v/o hold fp16 data (half the buffer used)
__device__ float g_q[MROWS * DD];
__device__ float g_k[MROWS * DD];
__device__ float g_v[MROWS * DD];
__device__ float g_o[MROWS * DD];

// ---------------------------------------------------------------------------
// Helpers
// ---------------------------------------------------------------------------
static __device__ __forceinline__ uint32_t h2pack(float lo, float hi) {
    uint32_t r;
    asm("cvt.rn.f16x2.f32 %0, %1, %2;" : "=r"(r) : "f"(hi), "f"(lo));
    return r;
}

static __device__ __forceinline__ float ex2f(float x) {
    float r;
    asm("ex2.approx.f32 %0, %1;" : "=f"(r) : "f"(x));
    return r;
}

static __device__ __forceinline__ uint32_t cvta_smem(const void* p) {
    uint32_t a;
    asm("{ .reg .u64 t; cvta.to.shared.u64 t, %1; cvt.u32.u64 %0, t; }"
        : "=r"(a) : "l"(p));
    return a;
}

// fp16 m16n8k16, fp32 accumulate
static __device__ __forceinline__ void mma_f16(float c[4], const uint32_t a[4],
                                               uint32_t b0, uint32_t b1) {
    asm volatile(
        "mma.sync.aligned.m16n8k16.row.col.f32.f16.f16.f32 "
        "{%0,%1,%2,%3}, {%4,%5,%6,%7}, {%8,%9}, {%0,%1,%2,%3};"
        : "+f"(c[0]), "+f"(c[1]), "+f"(c[2]), "+f"(c[3])
        : "r"(a[0]), "r"(a[1]), "r"(a[2]), "r"(a[3]), "r"(b0), "r"(b1));
}

static __device__ __forceinline__ void ldsm_x4(uint32_t r[4], uint32_t addr) {
    asm volatile("ldmatrix.sync.aligned.m8n8.x4.shared.b16 {%0,%1,%2,%3}, [%4];"
        : "=r"(r[0]), "=r"(r[1]), "=r"(r[2]), "=r"(r[3]) : "r"(addr));
}

static __device__ __forceinline__ void ldsm_x4t(uint32_t r[4], uint32_t addr) {
    asm volatile("ldmatrix.sync.aligned.m8n8.x4.trans.shared.b16 {%0,%1,%2,%3}, [%4];"
        : "=r"(r[0]), "=r"(r[1]), "=r"(r[2]), "=r"(r[3]) : "r"(addr));
}

#define SCALE_LOG2E 0.180336880f   // 0.125 * log2(e)

// ---------------------------------------------------------------------------
// Fused fp16 mma.sync GEMM: C[z] = (A[z] @ W[z]^T + bias[z]) * outScale[z].
// CTA 128x128, BK=16, 128 threads (4 warps of 64x64).
// AF16: A is fp16 bits (bit-copy staging) vs fp32 (convert in staging).
// OUT16: write fp16 packed output vs fp32.
// ---------------------------------------------------------------------------
#define BK 16
#define HBUF 1024   // words per matrix per buffer (128 rows * 32B)

template <int AF16, int OUT16>
__global__ __launch_bounds__(128, 2) void gemm_f16_kernel(
    const void* __restrict__ A0v, const void* __restrict__ A1v, const void* __restrict__ A2v,
    const float* __restrict__ W0, const float* __restrict__ W1, const float* __restrict__ W2,
    const float* __restrict__ b0p, const float* __restrict__ b1p, const float* __restrict__ b2p,
    void* __restrict__ C0v, void* __restrict__ C1v, void* __restrict__ C2v,
    float s0, float s1, float s2)
{
    __shared__ uint32_t As[2][HBUF];
    __shared__ uint32_t Bs[2][HBUF];

    const int z = blockIdx.z;
    const void* Av = (z == 0) ? A0v : (z == 1) ? A1v : A2v;
    const float* W = (z == 0) ? W0 : (z == 1) ? W1 : W2;
    const float* bias = (z == 0) ? b0p : (z == 1) ? b1p : b2p;
    void* Cv = (z == 0) ? C0v : (z == 1) ? C1v : C2v;
    const float outScale = (z == 0) ? s0 : (z == 1) ? s1 : s2;

    const int tid = threadIdx.x;
    const int lane = tid & 31;
    const int wid = tid >> 5;
    const int wm = wid & 1;
    const int wn = wid >> 1;
    const int l4 = lane >> 2;
    const int lm = lane & 3;
    const int rowBase = blockIdx.y * 128;
    const int colBase = blockIdx.x * 128;

    const uint32_t asb = cvta_smem(As);
    const uint32_t bsb = cvta_smem(Bs);

    uint32_t aOff[4], bOff[4];
#pragma unroll
    for (int mt = 0; mt < 4; mt++) {
        uint32_t r = wm * 64 + mt * 16 + (lane & 15);
        uint32_t ck = lane >> 4;
        aOff[mt] = r * 32 + ((ck ^ ((r >> 2) & 1)) << 4);
    }
#pragma unroll
    for (int t = 0; t < 4; t++) {
        uint32_t r = wn * 64 + t * 16 + (lane & 7) + 8 * ((lane >> 4) & 1);
        uint32_t ck = (lane >> 3) & 1;
        bOff[t] = r * 32 + ((ck ^ ((r >> 2) & 1)) << 4);
    }

    float acc[4][8][4];
#pragma unroll
    for (int mt = 0; mt < 4; mt++)
#pragma unroll
        for (int nt = 0; nt < 8; nt++)
#pragma unroll
            for (int r = 0; r < 4; r++) acc[mt][nt][r] = 0.0f;

    // global prefetch regs
    float4 ra[4], rb[4];
    uint4 ha[2];
    auto loadg = [&](int ic) {
        const int kOff = ic * BK;
        if (AF16) {
            const uint32_t* A16 = (const uint32_t*)Av;
#pragma unroll
            for (int i = 0; i < 2; i++) {
                int fi = tid + 128 * i;
                int row = fi >> 1;
                int ch = fi & 1;
                ha[i] = *(const uint4*)(A16 + (size_t)(rowBase + row) * (DD / 2)
                                         + ic * 8 + ch * 4);
            }
        } else {
            const float* A = (const float*)Av;
#pragma unroll
            for (int i = 0; i < 4; i++) {
                int fi = tid + 128 * i;
                int row = fi >> 2;
                int q4 = fi & 3;
                ra[i] = *(const float4*)(A + (size_t)(rowBase + row) * DD + kOff + q4 * 4);
            }
        }
#pragma unroll
        for (int i = 0; i < 4; i++) {
            int fi = tid + 128 * i;
            int row = fi >> 2;
            int q4 = fi & 3;
            rb[i] = *(const float4*)(W + (size_t)(colBase + row) * DD + kOff + q4 * 4);
        }
    };

    loadg(0);
    const int nChunks = DD / BK;   // 64

    for (int ic = 0; ic < nChunks; ic++) {
        const int buf = ic & 1;
        const uint32_t bufB = buf * (HBUF * 4);
        if (AF16) {
#pragma unroll
            for (int i = 0; i < 2; i++) {
                int fi = tid + 128 * i;
                uint32_t row = fi >> 1;
                uint32_t ch = fi & 1;
                uint32_t byteOff = row * 32 + ((ch ^ ((row >> 2) & 1)) << 4);
                asm volatile("st.shared.v4.b32 [%0], {%1,%2,%3,%4};"
                    :: "r"(asb + bufB + byteOff),
                       "r"(ha[i].x), "r"(ha[i].y), "r"(ha[i].z), "r"(ha[i].w)
                    : "memory");
            }
        } else {
#pragma unroll
            for (int i = 0; i < 4; i++) {
                int fi = tid + 128 * i;
                uint32_t row = fi >> 2;
                uint32_t q4 = fi & 3;
                uint32_t byteOff = row * 32
                    + ((((q4 >> 1) ^ ((row >> 2) & 1))) << 4) + (q4 & 1) * 8;
                uint32_t a0 = h2pack(ra[i].x, ra[i].y);
                uint32_t a1 = h2pack(ra[i].z, ra[i].w);
                asm volatile("st.shared.v2.b32 [%0], {%1,%2};"
                    :: "r"(asb + bufB + byteOff), "r"(a0), "r"(a1) : "memory");
            }
        }
#pragma unroll
        for (int i = 0; i < 4; i++) {
            int fi = tid + 128 * i;
            uint32_t row = fi >> 2;
            uint32_t q4 = fi & 3;
            uint32_t byteOff = row * 32
                + ((((q4 >> 1) ^ ((row >> 2) & 1))) << 4) + (q4 & 1) * 8;
            uint32_t b0 = h2pack(rb[i].x, rb[i].y);
            uint32_t b1 = h2pack(rb[i].z, rb[i].w);
            asm volatile("st.shared.v2.b32 [%0], {%1,%2};"
                :: "r"(bsb + bufB + byteOff), "r"(b0), "r"(b1) : "memory");
        }
        __syncthreads();

        if (ic + 1 < nChunks) loadg(ic + 1);

        {
            uint32_t af[4][4];
#pragma unroll
            for (int mt = 0; mt < 4; mt++)
                ldsm_x4(af[mt], asb + bufB + aOff[mt]);
#pragma unroll
            for (int t = 0; t < 4; t++) {
                uint32_t bb[4];
                ldsm_x4(bb, bsb + bufB + bOff[t]);
#pragma unroll
                for (int mt = 0; mt < 4; mt++) {
                    mma_f16(acc[mt][2 * t],     af[mt], bb[0], bb[1]);
                    mma_f16(acc[mt][2 * t + 1], af[mt], bb[2], bb[3]);
                }
            }
        }
        // no trailing sync: double-buffered smem
    }

    // epilogue
#pragma unroll
    for (int nt = 0; nt < 8; nt++) {
        int c = colBase + wn * 64 + nt * 8 + 2 * lm;
        float2 bv = *(const float2*)(bias + c);
#pragma unroll
        for (int mt = 0; mt < 4; mt++) {
            int r = rowBase + wm * 64 + mt * 16 + l4;
            float o00 = (acc[mt][nt][0] + bv.x) * outScale;
            float o01 = (acc[mt][nt][1] + bv.y) * outScale;
            float o10 = (acc[mt][nt][2] + bv.x) * outScale;
            float o11 = (acc[mt][nt][3] + bv.y) * outScale;
            if (OUT16) {
                uint32_t* C16 = (uint32_t*)Cv;
                C16[(size_t)r * (DD / 2) + c / 2]       = h2pack(o00, o01);
                C16[(size_t)(r + 8) * (DD / 2) + c / 2] = h2pack(o10, o11);
            } else {
                float* C = (float*)Cv;
                *(float2*)(C + (size_t)r * DD + c)       = make_float2(o00, o01);
                *(float2*)(C + (size_t)(r + 8) * DD + c) = make_float2(o10, o11);
            }
        }
    }
}

// ---------------------------------------------------------------------------
// Flash attention (causal), fp16 m16n8k16 mma, fp32 accum + softmax.
// R12 loop structure: 128 threads (4 warps x 16 q-rows), 64 q-rows/CTA,
// 64-key tiles, double-buffered K/V smem (bit-copy fp16 staging), single sync
// per tile, log2-domain softmax (Q pre-scaled by scale*log2e in projection).
// V used row-major via ldmatrix.trans. Smem: K[2]8K + V[2]8K + P 8K = 40KB.
// ---------------------------------------------------------------------------
#define KTB16 8192
#define FLASH_SMEM (5 * KTB16)   // 40960 B

__global__ __launch_bounds__(128, 2) void flash_f16_kernel(
    const uint32_t* __restrict__ Qg, const uint32_t* __restrict__ Kg,
    const uint32_t* __restrict__ Vg, uint32_t* __restrict__ Og)
{
    extern __shared__ uint32_t sm[];

    const int tid = threadIdx.x;
    const int lane = tid & 31;
    const int wid = tid >> 5;
    const int l4 = lane >> 2;
    const int lm = lane & 3;

    const int qt = (gridDim.x - 1) - blockIdx.x;   // heavy tiles first
    const int h  = blockIdx.y;
    const int b  = blockIdx.z;
    const int q0 = qt * 64;

    // halves-based bases, expressed in uint32 units (2 halves per u32)
    const size_t base32 = ((size_t)b * SS * DD + (size_t)h * DK) / 2;
    const int RW32 = DD / 2;   // row stride in u32

    const int gr0 = q0 + wid * 16 + l4;
    const int prow = wid * 16 + l4;

    const uint32_t smb = cvta_smem(sm);
    const uint32_t psb = smb + 4 * KTB16;

    // K (non-trans B): row r over n, 128B rows, swizzle (r&7)
    uint32_t kRow[4], kSw[4];
#pragma unroll
    for (int t = 0; t < 4; t++) {
        uint32_t r = t * 16 + (lane & 7) + 8 * ((lane >> 4) & 1);
        kRow[t] = r * 128;
        kSw[t] = r & 7;
    }
    const uint32_t cbb = (lane >> 3) & 1;
    // V (trans B): row n = ks*16 + nOff, chunk (t*2 + hi16) ^ (nOff&7)
    const uint32_t nOff = 8 * ((lane >> 3) & 1) + (lane & 7);
    const uint32_t vHi = (lane >> 4) & 1;
    uint32_t vOff[4];
#pragma unroll
    for (int t = 0; t < 4; t++)
        vOff[t] = nOff * 128 + (((t * 2 + vHi) ^ (nOff & 7)) << 4);
    // P (A frag): row wid*16+(lane&15), chunk ks*2+(lane>>4), swizzle row&7
    const uint32_t rowP = wid * 16 + (lane & 15);
    const uint32_t pRowOff = rowP * 128;
    const uint32_t swP = rowP & 7;
    const uint32_t ca = lane >> 4;
    // P writes (rows prow, prow+8): chunk nt ^ (row&7), in-chunk lm*4
    const uint32_t pw0 = psb + prow * 128 + lm * 4;
    const uint32_t pw1 = psb + (prow + 8) * 128 + lm * 4;
    const uint32_t swW0 = prow & 7;
    const uint32_t swW1 = (prow + 8) & 7;

    // Q fragments: bit-copy of fp16 (pre-scaled by scale*log2e in projection)
    uint32_t qf[4][4];
    {
        const uint32_t* q0p = Qg + base32 + (size_t)gr0 * RW32;
        const uint32_t* q1p = Qg + base32 + (size_t)(gr0 + 8) * RW32;
#pragma unroll
        for (int ks = 0; ks < 4; ks++) {
            qf[ks][0] = q0p[ks * 8 + lm];
            qf[ks][1] = q1p[ks * 8 + lm];
            qf[ks][2] = q0p[ks * 8 + 4 + lm];
            qf[ks][3] = q1p[ks * 8 + 4 + lm];
        }
    }

    float oacc[8][4];
#pragma unroll
    for (int dt = 0; dt < 8; dt++)
#pragma unroll
        for (int r = 0; r < 4; r++) oacc[dt][r] = 0.0f;
    float m0 = -1e30f, m1 = -1e30f, l0 = 0.0f, l1 = 0.0f;

    // K/V tile register prefetch: 4 uint4 each (64 rows x 128B per tile)
    uint4 kr[4], vv[4];
    const uint4* Ku4 = (const uint4*)Kg;
    const uint4* Vu4 = (const uint4*)Vg;
    const size_t base128 = base32 / 4;    // uint4 units
    const int RW128 = RW32 / 4;           // 128
    auto load_kv = [&](int kt) {
        const int k0 = kt * 64;
#pragma unroll
        for (int i = 0; i < 4; i++) {
            int fi = tid + 128 * i;
            int row = fi >> 3;
            int ch = fi & 7;
            size_t idx = base128 + (size_t)(k0 + row) * RW128 + ch;
            kr[i] = Ku4[idx];
            vv[i] = Vu4[idx];
        }
    };
    auto store_kv = [&](int buf) {
        const uint32_t kb = smb + buf * KTB16;
        const uint32_t vb = smb + (2 + buf) * KTB16;
#pragma unroll
        for (int i = 0; i < 4; i++) {
            int fi = tid + 128 * i;
            uint32_t row = fi >> 3;
            uint32_t ch = fi & 7;
            uint32_t off = row * 128 + ((ch ^ (row & 7)) << 4);
            asm volatile("st.shared.v4.b32 [%0], {%1,%2,%3,%4};"
                :: "r"(kb + off), "r"(kr[i].x), "r"(kr[i].y), "r"(kr[i].z), "r"(kr[i].w)
                : "memory");
            asm volatile("st.shared.v4.b32 [%0], {%1,%2,%3,%4};"
                :: "r"(vb + off), "r"(vv[i].x), "r"(vv[i].y), "r"(vv[i].z), "r"(vv[i].w)
                : "memory");
        }
    };

    load_kv(0);
    store_kv(0);
    __syncthreads();

    const int nkt = qt + 1;
    for (int kt = 0; kt < nkt; kt++) {
        const int k0 = kt * 64;
        const int buf = kt & 1;
        const uint32_t kBuf = smb + buf * KTB16;
        const uint32_t vBuf = smb + (2 + buf) * KTB16;

        // S = Q @ K^T  (scores already in log2 domain via pre-scaled Q)
        float sf[8][4];
#pragma unroll
        for (int nt = 0; nt < 8; nt++)
#pragma unroll
            for (int r = 0; r < 4; r++) sf[nt][r] = 0.0f;

#pragma unroll
        for (int ks = 0; ks < 4; ks++) {
            const uint32_t ck = cbb + ks * 2;
#pragma unroll
            for (int t = 0; t < 4; t++) {
                uint32_t bb[4];
                ldsm_x4(bb, kBuf + kRow[t] + ((ck ^ kSw[t]) << 4));
                mma_f16(sf[2 * t],     qf[ks], bb[0], bb[1]);
                mma_f16(sf[2 * t + 1], qf[ks], bb[2], bb[3]);
            }
        }

        if (kt + 1 < nkt) load_kv(kt + 1);   // hide LDG under softmax+PV

        if (k0 + 63 > q0 + wid * 16) {
#pragma unroll
            for (int nt = 0; nt < 8; nt++) {
                int c = k0 + nt * 8 + 2 * lm;
                if (c     > gr0)     sf[nt][0] = -1e30f;
                if (c + 1 > gr0)     sf[nt][1] = -1e30f;
                if (c     > gr0 + 8) sf[nt][2] = -1e30f;
                if (c + 1 > gr0 + 8) sf[nt][3] = -1e30f;
            }
        }

        // online softmax in log2 domain
        float rm0 = -1e30f, rm1 = -1e30f;
#pragma unroll
        for (int nt = 0; nt < 8; nt++) {
            rm0 = fmaxf(rm0, fmaxf(sf[nt][0], sf[nt][1]));
            rm1 = fmaxf(rm1, fmaxf(sf[nt][2], sf[nt][3]));
        }
#pragma unroll
        for (int off = 1; off <= 2; off <<= 1) {
            rm0 = fmaxf(rm0, __shfl_xor_sync(0xffffffffu, rm0, off));
            rm1 = fmaxf(rm1, __shfl_xor_sync(0xffffffffu, rm1, off));
        }
        float nm0 = fmaxf(m0, rm0), nm1 = fmaxf(m1, rm1);
        float a0 = ex2f(m0 - nm0), a1 = ex2f(m1 - nm1);
        float rs0 = 0.0f, rs1 = 0.0f;
#pragma unroll
        for (int nt = 0; nt < 8; nt++) {
            sf[nt][0] = ex2f(sf[nt][0] - nm0);
            sf[nt][1] = ex2f(sf[nt][1] - nm0);
            sf[nt][2] = ex2f(sf[nt][2] - nm1);
            sf[nt][3] = ex2f(sf[nt][3] - nm1);
            rs0 += sf[nt][0] + sf[nt][1];
            rs1 += sf[nt][2] + sf[nt][3];
        }
#pragma unroll
        for (int off = 1; off <= 2; off <<= 1) {
            rs0 += __shfl_xor_sync(0xffffffffu, rs0, off);
            rs1 += __shfl_xor_sync(0xffffffffu, rs1, off);
        }
        l0 = l0 * a0 + rs0;  m0 = nm0;
        l1 = l1 * a1 + rs1;  m1 = nm1;
#pragma unroll
        for (int dt = 0; dt < 8; dt++) {
            oacc[dt][0] *= a0; oacc[dt][1] *= a0;
            oacc[dt][2] *= a1; oacc[dt][3] *= a1;
        }

        // P -> smem (fp16 pairs), swizzled, warp-private rows
#pragma unroll
        for (int nt = 0; nt < 8; nt++) {
            uint32_t p0 = h2pack(sf[nt][0], sf[nt][1]);
            uint32_t p1 = h2pack(sf[nt][2], sf[nt][3]);
            asm volatile("st.shared.b32 [%0], %1;"
                :: "r"(pw0 + (((uint32_t)nt ^ swW0) << 4)), "r"(p0) : "memory");
            asm volatile("st.shared.b32 [%0], %1;"
                :: "r"(pw1 + (((uint32_t)nt ^ swW1) << 4)), "r"(p1) : "memory");
        }
        __syncwarp();

        // O += P @ V  (V row-major, trans ldsm B-frags)
#pragma unroll
        for (int ks = 0; ks < 4; ks++) {
            uint32_t af[4];
            ldsm_x4(af, psb + pRowOff + (((ca + ks * 2) ^ swP) << 4));
            const uint32_t vkB = ks * 2048;   // ks*16 rows * 128B
#pragma unroll
            for (int t = 0; t < 4; t++) {
                uint32_t bb[4];
                ldsm_x4t(bb, vBuf + vkB + vOff[t]);
                mma_f16(oacc[2 * t],     af, bb[0], bb[1]);
                mma_f16(oacc[2 * t + 1], af, bb[2], bb[3]);
            }
        }

        if (kt + 1 < nkt) {
            store_kv(buf ^ 1);
            __syncthreads();   // single sync per tile
        }
    }

    // normalize + write O as fp16 pairs
    float inv0 = 1.0f / l0, inv1 = 1.0f / l1;
    uint32_t* o0p = Og + base32 + (size_t)gr0 * RW32;
    uint32_t* o1p = Og + base32 + (size_t)(gr0 + 8) * RW32;
#pragma unroll
    for (int dt = 0; dt < 8; dt++) {
        o0p[dt * 4 + lm] = h2pack(oacc[dt][0] * inv0, oacc[dt][1] * inv0);
        o1p[dt * 4 + lm] = h2pack(oacc[dt][2] * inv1, oacc[dt][3] * inv1);
    }
}

// ---------------------------------------------------------------------------
// Launch
// ---------------------------------------------------------------------------
extern "C" void kernel_launch(void* const* d_in, const int* in_sizes, int n_in,
                              void* d_out, int out_size)
{
    const float* query = (const float*)d_in[0];
    const float* key   = (const float*)d_in[1];
    const float* value = (const float*)d_in[2];
    const float* wq = (const float*)d_in[3];
    const float* bq = (const float*)d_in[4];
    const float* wk = (const float*)d_in[5];
    const float* bk = (const float*)d_in[6];
    const float* wv = (const float*)d_in[7];
    const float* bv = (const float*)d_in[8];
    const float* wo = (const float*)d_in[9];
    const float* bo = (const float*)d_in[10];
    float* out = (float*)d_out;

    float *q_s, *k_s, *v_s, *o_s;
    cudaGetSymbolAddress((void**)&q_s, g_q);
    cudaGetSymbolAddress((void**)&k_s, g_k);
    cudaGetSymbolAddress((void**)&v_s, g_v);
    cudaGetSymbolAddress((void**)&o_s, g_o);

    cudaFuncSetAttribute(flash_f16_kernel,
                         cudaFuncAttributeMaxDynamicSharedMemorySize, FLASH_SMEM);

    // 1. fused q/k/v projections -> fp16 outputs; Q pre-scaled by scale*log2e
    dim3 gproj3(DD / 128, MROWS / 128, 3);
    gemm_f16_kernel<0, 1><<<gproj3, 128>>>(
        query, key, value, wq, wk, wv, bq, bk, bv,
        q_s, k_s, v_s, SCALE_LOG2E, 1.0f, 1.0f);

    // 2. flash attention (fp16 MMA end-to-end, fp32 softmax/accum)
    dim3 gattn(SS / 64, HH, BB);   // (32, 16, 2) = 1024 CTAs
    flash_f16_kernel<<<gattn, 128, FLASH_SMEM>>>(
        (const uint32_t*)q_s, (const uint32_t*)k_s, (const uint32_t*)v_s,
        (uint32_t*)o_s);

    // 3. output projection (A = fp16 O, bit-copy staging; fp32 final output)
    dim3 gproj1(DD / 128, MROWS / 128, 1);
    gemm_f16_kernel<1, 0><<<gproj1, 128>>>(
        o_s, o_s, o_s, wo, wo, wo, bo, bo, bo,
        out, out, out, 1.0f, 1.0f, 1.0f);
}